// round 1
// baseline (speedup 1.0000x reference)
#include <cuda_runtime.h>
#include <math.h>

#define B_   2
#define T_   2048
#define C_   4096
#define H_   32
#define KVH_ 8
#define HS_  128
#define GROUPS (H_/KVH_)

// Scratch (allowed: __device__ globals, no runtime allocation)
__device__ float g_Q[(size_t)B_*T_*H_*HS_];
__device__ float g_K[(size_t)B_*T_*KVH_*HS_];
__device__ float g_V[(size_t)B_*T_*KVH_*HS_];
__device__ float g_Y[(size_t)B_*T_*H_*HS_];

// ---------------------------------------------------------------------------
// SGEMM with bias: C[M,N] = A[M,K] @ B[K,N] + bias[N]
// BM=BN=128, BK=8, 256 threads, 8x8 micro-tile per thread.
// ---------------------------------------------------------------------------
__global__ __launch_bounds__(256) void sgemm_bias(
    int M, int N, int K,
    const float* __restrict__ A, const float* __restrict__ Bm,
    const float* __restrict__ bias, float* __restrict__ C)
{
    const int BM = 128, BN = 128, BK = 8, TM = 8, TN = 8;
    __shared__ float As[BK * BM];   // transposed: As[k*BM + m]
    __shared__ float Bs[BK * BN];   // Bs[k*BN + n]

    int tid  = threadIdx.x;
    int brow = blockIdx.y, bcol = blockIdx.x;

    const float* Ab = A + (size_t)brow * BM * K;
    const float* Bb = Bm + (size_t)bcol * BN;
    float*       Cb = C + (size_t)brow * BM * N + (size_t)bcol * BN;

    int aRow = tid >> 1;           // 0..127
    int aCol = (tid & 1) * 4;      // 0 or 4
    int bRow = tid >> 5;           // 0..7
    int bCol = (tid & 31) * 4;     // 0..124
    int tRow = (tid >> 4) * TM;
    int tCol = (tid & 15) * TN;

    float acc[TM][TN];
    #pragma unroll
    for (int i = 0; i < TM; i++)
        #pragma unroll
        for (int j = 0; j < TN; j++) acc[i][j] = 0.f;

    for (int k0 = 0; k0 < K; k0 += BK) {
        float4 av = *(const float4*)(Ab + (size_t)aRow * K + k0 + aCol);
        As[(aCol + 0) * BM + aRow] = av.x;
        As[(aCol + 1) * BM + aRow] = av.y;
        As[(aCol + 2) * BM + aRow] = av.z;
        As[(aCol + 3) * BM + aRow] = av.w;
        *(float4*)(Bs + bRow * BN + bCol) =
            *(const float4*)(Bb + (size_t)(k0 + bRow) * N + bCol);
        __syncthreads();

        #pragma unroll
        for (int k = 0; k < BK; k++) {
            float regM[TM], regN[TN];
            *(float4*)(regM)     = *(float4*)(As + k * BM + tRow);
            *(float4*)(regM + 4) = *(float4*)(As + k * BM + tRow + 4);
            *(float4*)(regN)     = *(float4*)(Bs + k * BN + tCol);
            *(float4*)(regN + 4) = *(float4*)(Bs + k * BN + tCol + 4);
            #pragma unroll
            for (int i = 0; i < TM; i++)
                #pragma unroll
                for (int j = 0; j < TN; j++)
                    acc[i][j] += regM[i] * regN[j];
        }
        __syncthreads();
    }

    #pragma unroll
    for (int i = 0; i < TM; i++) {
        #pragma unroll
        for (int j = 0; j < TN; j += 4) {
            float4 bv = *(const float4*)(bias + (size_t)bcol * BN + tCol + j);
            float4 o;
            o.x = acc[i][j + 0] + bv.x;
            o.y = acc[i][j + 1] + bv.y;
            o.z = acc[i][j + 2] + bv.z;
            o.w = acc[i][j + 3] + bv.w;
            *(float4*)(Cb + (size_t)(tRow + i) * N + tCol + j) = o;
        }
    }
}

// ---------------------------------------------------------------------------
// RoPE in place on X: [B*T, heads, 128]. One thread per (row, head, d<64).
// ---------------------------------------------------------------------------
__global__ void rope_kernel(float* __restrict__ X, int heads, long total)
{
    long idx = (long)blockIdx.x * blockDim.x + threadIdx.x;
    if (idx >= total) return;
    int d = (int)(idx & 63);
    long rh = idx >> 6;                 // row*heads + h
    long row = rh / heads;
    int t = (int)(row % T_);

    float inv = powf(10000.0f, -(float)d * (1.0f / 64.0f));
    float ang = (float)t * inv;
    float c = cosf(ang), s = sinf(ang);

    float* p = X + rh * HS_;
    float x1 = p[d], x2 = p[d + 64];
    p[d]      = x1 * c - x2 * s;
    p[d + 64] = x2 * c + x1 * s;
}

// ---------------------------------------------------------------------------
// Causal flash attention, fp32.
// Grid: (T/64, H, B), 256 threads.  Q tile 64x128, K/V tiles 64x128.
// K stored transposed in smem ([d][kcol]) for conflict-free QK^T.
// S stored 64x65 (padded) for conflict-free softmax.
// ---------------------------------------------------------------------------
#define QT 64
#define KT 64
#define SPAD 65

__global__ __launch_bounds__(256) void attn_kernel(
    const float* __restrict__ Q, const float* __restrict__ K,
    const float* __restrict__ V, float* __restrict__ Y)
{
    extern __shared__ float sm[];
    float* Qs = sm;                       // [64][128]
    float* Ks = Qs + QT * HS_;            // transposed [128][64]
    float* Vs = Ks + HS_ * KT;            // [64][128]
    float* Ss = Vs + KT * HS_;            // [64][65]
    __shared__ float m_s[QT], l_s[QT], alpha_s[QT];

    int tid = threadIdx.x;
    int qt = blockIdx.x, h = blockIdx.y, b = blockIdx.z;
    int kh = h / GROUPS;
    int sRow = tid >> 4;    // 0..15
    int sCol = tid & 15;    // 0..15
    const float scale = 0.08838834764831845f;   // 1/sqrt(128)

    // Load Q tile
    for (int i = tid; i < QT * HS_ / 4; i += 256) {
        int r  = i >> 5;
        int c4 = (i & 31) * 4;
        *(float4*)(Qs + r * HS_ + c4) =
            *(const float4*)(Q + ((size_t)(b * T_ + qt * QT + r) * H_ + h) * HS_ + c4);
    }
    if (tid < QT) { m_s[tid] = -INFINITY; l_s[tid] = 0.f; }

    float acc[4][8];
    #pragma unroll
    for (int i = 0; i < 4; i++)
        #pragma unroll
        for (int j = 0; j < 8; j++) acc[i][j] = 0.f;

    for (int jt = 0; jt <= qt; jt++) {
        __syncthreads();   // previous PV done with Ss/Vs; Q load done (first iter)

        // Load K (transposed) and V tiles
        for (int i = tid; i < KT * HS_ / 4; i += 256) {
            int r  = i >> 5;
            int c4 = (i & 31) * 4;
            size_t gbase = ((size_t)(b * T_ + jt * KT + r) * KVH_ + kh) * HS_ + c4;
            float4 kv = *(const float4*)(K + gbase);
            Ks[(c4 + 0) * KT + r] = kv.x;
            Ks[(c4 + 1) * KT + r] = kv.y;
            Ks[(c4 + 2) * KT + r] = kv.z;
            Ks[(c4 + 3) * KT + r] = kv.w;
            *(float4*)(Vs + r * HS_ + c4) = *(const float4*)(V + gbase);
        }
        __syncthreads();

        // S = scale * Q K^T  (each thread 4x4)
        float s44[4][4];
        #pragma unroll
        for (int i = 0; i < 4; i++)
            #pragma unroll
            for (int j = 0; j < 4; j++) s44[i][j] = 0.f;

        #pragma unroll 16
        for (int k = 0; k < HS_; k++) {
            float4 kk = *(float4*)(Ks + k * KT + sCol * 4);
            float q0 = Qs[(sRow * 4 + 0) * HS_ + k];
            float q1 = Qs[(sRow * 4 + 1) * HS_ + k];
            float q2 = Qs[(sRow * 4 + 2) * HS_ + k];
            float q3 = Qs[(sRow * 4 + 3) * HS_ + k];
            s44[0][0] += q0 * kk.x; s44[0][1] += q0 * kk.y; s44[0][2] += q0 * kk.z; s44[0][3] += q0 * kk.w;
            s44[1][0] += q1 * kk.x; s44[1][1] += q1 * kk.y; s44[1][2] += q1 * kk.z; s44[1][3] += q1 * kk.w;
            s44[2][0] += q2 * kk.x; s44[2][1] += q2 * kk.y; s44[2][2] += q2 * kk.z; s44[2][3] += q2 * kk.w;
            s44[3][0] += q3 * kk.x; s44[3][1] += q3 * kk.y; s44[3][2] += q3 * kk.z; s44[3][3] += q3 * kk.w;
        }
        #pragma unroll
        for (int i = 0; i < 4; i++)
            #pragma unroll
            for (int j = 0; j < 4; j++)
                Ss[(sRow * 4 + i) * SPAD + sCol * 4 + j] = s44[i][j] * scale;
        __syncthreads();

        // Online softmax update (one thread per row)
        if (tid < QT) {
            int r = tid;
            int jmax = (jt == qt) ? (r + 1) : KT;   // causal: j <= global row
            float m_old = m_s[r];
            float mx = m_old;
            for (int j = 0; j < jmax; j++) mx = fmaxf(mx, Ss[r * SPAD + j]);
            float a = expf(m_old - mx);             // 0 on first tile (m_old = -inf)
            float lsum = 0.f;
            for (int j = 0; j < KT; j++) {
                float p = (j < jmax) ? expf(Ss[r * SPAD + j] - mx) : 0.f;
                Ss[r * SPAD + j] = p;
                lsum += p;
            }
            l_s[r] = l_s[r] * a + lsum;
            m_s[r] = mx;
            alpha_s[r] = a;
        }
        __syncthreads();

        // O = O*alpha + P @ V  (each thread 4 rows x 8 cols)
        #pragma unroll
        for (int i = 0; i < 4; i++) {
            float a = alpha_s[sRow * 4 + i];
            #pragma unroll
            for (int j = 0; j < 8; j++) acc[i][j] *= a;
        }
        #pragma unroll 8
        for (int j = 0; j < KT; j++) {
            float4 v0 = *(float4*)(Vs + j * HS_ + sCol * 8);
            float4 v1 = *(float4*)(Vs + j * HS_ + sCol * 8 + 4);
            #pragma unroll
            for (int i = 0; i < 4; i++) {
                float p = Ss[(sRow * 4 + i) * SPAD + j];
                acc[i][0] += p * v0.x; acc[i][1] += p * v0.y;
                acc[i][2] += p * v0.z; acc[i][3] += p * v0.w;
                acc[i][4] += p * v1.x; acc[i][5] += p * v1.y;
                acc[i][6] += p * v1.z; acc[i][7] += p * v1.w;
            }
        }
    }

    // Normalize and write Y: [B*T, H*HS]
    #pragma unroll
    for (int i = 0; i < 4; i++) {
        int r = sRow * 4 + i;
        float inv_l = 1.f / l_s[r];
        float4 o0, o1;
        o0.x = acc[i][0] * inv_l; o0.y = acc[i][1] * inv_l;
        o0.z = acc[i][2] * inv_l; o0.w = acc[i][3] * inv_l;
        o1.x = acc[i][4] * inv_l; o1.y = acc[i][5] * inv_l;
        o1.z = acc[i][6] * inv_l; o1.w = acc[i][7] * inv_l;
        size_t base = (size_t)(b * T_ + qt * QT + r) * (H_ * HS_) + h * HS_ + sCol * 8;
        *(float4*)(Y + base)     = o0;
        *(float4*)(Y + base + 4) = o1;
    }
}

// ---------------------------------------------------------------------------
extern "C" void kernel_launch(void* const* d_in, const int* in_sizes, int n_in,
                              void* d_out, int out_size)
{
    const float* q_x  = (const float*)d_in[0];
    const float* kv_x = (const float*)d_in[1];
    const float* Wq   = (const float*)d_in[2];
    const float* bq   = (const float*)d_in[3];
    const float* Wk   = (const float*)d_in[4];
    const float* bk   = (const float*)d_in[5];
    const float* Wv   = (const float*)d_in[6];
    const float* bv   = (const float*)d_in[7];
    const float* Wo   = (const float*)d_in[8];
    const float* bo   = (const float*)d_in[9];
    float* out = (float*)d_out;

    float *qp, *kp, *vp, *yp;
    cudaGetSymbolAddress((void**)&qp, g_Q);
    cudaGetSymbolAddress((void**)&kp, g_K);
    cudaGetSymbolAddress((void**)&vp, g_V);
    cudaGetSymbolAddress((void**)&yp, g_Y);

    const int M = B_ * T_;   // 4096

    // Projections
    dim3 gq(C_ / 128, M / 128);                 // (32, 32)
    sgemm_bias<<<gq, 256>>>(M, H_ * HS_, C_, q_x, Wq, bq, qp);
    dim3 gkv((KVH_ * HS_) / 128, M / 128);      // (8, 32)
    sgemm_bias<<<gkv, 256>>>(M, KVH_ * HS_, C_, kv_x, Wk, bk, kp);
    sgemm_bias<<<gkv, 256>>>(M, KVH_ * HS_, C_, kv_x, Wv, bv, vp);

    // RoPE
    long tq = (long)B_ * T_ * H_ * 64;
    long tk = (long)B_ * T_ * KVH_ * 64;
    rope_kernel<<<(unsigned)((tq + 255) / 256), 256>>>(qp, H_, tq);
    rope_kernel<<<(unsigned)((tk + 255) / 256), 256>>>(kp, KVH_, tk);

    // Attention
    size_t smem = (size_t)(QT * HS_ + HS_ * KT + KT * HS_ + QT * SPAD) * sizeof(float);
    cudaFuncSetAttribute(attn_kernel, cudaFuncAttributeMaxDynamicSharedMemorySize, (int)smem);
    attn_kernel<<<dim3(T_ / QT, H_, B_), 256, smem>>>(qp, kp, vp, yp);

    // Output projection
    sgemm_bias<<<gq, 256>>>(M, C_, H_ * HS_, yp, Wo, bo, out);
}

// round 3
// speedup vs baseline: 1.9848x; 1.9848x over previous
#include <cuda_runtime.h>
#include <math.h>
#include <cstdint>

#define B_   2
#define T_   2048
#define C_   4096
#define H_   32
#define KVH_ 8
#define HS_  128
#define GROUPS (H_/KVH_)
#define GK    4096           // K dim of every GEMM here

// ---------------------------------------------------------------------------
// Scratch (__device__ globals; no runtime allocation)
// ---------------------------------------------------------------------------
__device__ float g_Q[(size_t)B_*T_*H_*HS_];
__device__ float g_K[(size_t)B_*T_*KVH_*HS_];
__device__ float g_V[(size_t)B_*T_*KVH_*HS_];
__device__ float g_Y[(size_t)B_*T_*H_*HS_];
__device__ float g_WqT[(size_t)C_*H_*HS_];      // [N=4096][K=4096]
__device__ float g_WkT[(size_t)C_*KVH_*HS_];    // [N=1024][K=4096]
__device__ float g_WvT[(size_t)C_*KVH_*HS_];
__device__ float g_WoT[(size_t)H_*HS_*C_];      // [N=4096][K=4096]

// ---------------------------------------------------------------------------
// Helpers
// ---------------------------------------------------------------------------
__device__ __forceinline__ uint32_t smem_to_u32(const void* p) {
    uint32_t a;
    asm("{ .reg .u64 t; cvta.to.shared.u64 t, %1; cvt.u32.u64 %0, t; }" : "=r"(a) : "l"(p));
    return a;
}

__device__ __forceinline__ uint32_t f2tf32(float x) {
    uint32_t u;
    asm("cvt.rna.tf32.f32 %0, %1;" : "=r"(u) : "f"(x));
    return u;
}

__device__ __forceinline__ void cp_async16(uint32_t smem_addr, const void* gptr) {
    asm volatile("cp.async.cg.shared.global [%0], [%1], 16;" :: "r"(smem_addr), "l"(gptr));
}
#define CP_COMMIT() asm volatile("cp.async.commit_group;" ::: "memory")
#define CP_WAIT(n)  asm volatile("cp.async.wait_group %0;" :: "n"(n) : "memory")

__device__ __forceinline__ void mma_tf32(
    float& d0, float& d1, float& d2, float& d3,
    uint32_t a0, uint32_t a1, uint32_t a2, uint32_t a3,
    uint32_t b0, uint32_t b1)
{
    asm volatile(
        "mma.sync.aligned.m16n8k8.row.col.f32.tf32.tf32.f32 "
        "{%0,%1,%2,%3}, {%4,%5,%6,%7}, {%8,%9}, {%0,%1,%2,%3};"
        : "+f"(d0), "+f"(d1), "+f"(d2), "+f"(d3)
        : "r"(a0), "r"(a1), "r"(a2), "r"(a3), "r"(b0), "r"(b1));
}

// ---------------------------------------------------------------------------
// Transpose: src [rows][cols] -> dst [cols][rows]
// ---------------------------------------------------------------------------
__global__ void transpose_kernel(const float* __restrict__ src, float* __restrict__ dst,
                                 int rows, int cols)
{
    __shared__ float tile[32][33];
    int c0 = blockIdx.x * 32, r0 = blockIdx.y * 32;
    int x = threadIdx.x;
    #pragma unroll
    for (int y = threadIdx.y; y < 32; y += 8)
        tile[y][x] = src[(size_t)(r0 + y) * cols + c0 + x];
    __syncthreads();
    #pragma unroll
    for (int y = threadIdx.y; y < 32; y += 8)
        dst[(size_t)(c0 + y) * rows + r0 + x] = tile[x][y];
}

// ---------------------------------------------------------------------------
// tf32 mma.sync GEMM + bias: C[M,N] = A[M,4096] @ BT[N,4096]^T + bias[N]
// BM=BN=128, BK=32, 256 threads (8 warps, warp tile 64x32), 4-stage cp.async.
// SMEM row stride 36 floats -> all fragment LDS patterns conflict-free.
// ---------------------------------------------------------------------------
#define SA        36
#define STAGES    4
#define STAGE_FLT (2 * 128 * SA)      // A block + B block per stage
#define GEMM_SMEM (STAGES * STAGE_FLT * 4)
#define KTILES    (GK / 32)           // 128

__global__ __launch_bounds__(256) void mma_gemm_bias(
    int N, const float* __restrict__ A, const float* __restrict__ BT,
    const float* __restrict__ bias, float* __restrict__ C)
{
    extern __shared__ float sm[];
    uint32_t sb = smem_to_u32(sm);

    int tid  = threadIdx.x;
    int lane = tid & 31, wid = tid >> 5;
    int wr = wid >> 2;           // 0..1 : 64-row slab
    int wc = wid & 3;            // 0..3 : 32-col slab
    int g  = lane >> 2;          // 0..7
    int tg = lane & 3;           // 0..3
    int m0 = blockIdx.y * 128, n0 = blockIdx.x * 128;

    int ldRow = tid >> 3;              // 0..31 per 256-thread pass -> x4 passes
    int ldC4  = (tid & 7) * 4;

    // acc[mt][nt][4]
    float acc[4][4][4];
    #pragma unroll
    for (int i = 0; i < 4; i++)
        #pragma unroll
        for (int j = 0; j < 4; j++)
            #pragma unroll
            for (int k = 0; k < 4; k++) acc[i][j][k] = 0.f;

    // ---- pipelined loads ----
    auto issue_tile = [&](int kt, int s) {
        const float* Ag = A  + (size_t)(m0) * GK + kt * 32;
        const float* Bg = BT + (size_t)(n0) * GK + kt * 32;
        uint32_t stA = sb + (uint32_t)(s * STAGE_FLT) * 4;
        uint32_t stB = stA + (uint32_t)(128 * SA) * 4;
        #pragma unroll
        for (int i = 0; i < 4; i++) {
            int row = ldRow + 32 * i;
            uint32_t soff = (uint32_t)(row * SA + ldC4) * 4;
            cp_async16(stA + soff, Ag + (size_t)row * GK + ldC4);
            cp_async16(stB + soff, Bg + (size_t)row * GK + ldC4);
        }
    };

    #pragma unroll
    for (int s = 0; s < STAGES - 1; s++) {
        issue_tile(s, s);
        CP_COMMIT();
    }
    CP_WAIT(STAGES - 2);
    __syncthreads();

    for (int kt = 0; kt < KTILES; kt++) {
        // prefetch tile kt+STAGES-1 into stage (kt+STAGES-1)%STAGES
        if (kt + STAGES - 1 < KTILES)
            issue_tile(kt + STAGES - 1, (kt + STAGES - 1) & (STAGES - 1));
        CP_COMMIT();

        // compute on stage kt%STAGES
        const float* As = sm + (kt & (STAGES - 1)) * STAGE_FLT;
        const float* Bs = As + 128 * SA;

        #pragma unroll
        for (int ks = 0; ks < 4; ks++) {
            int kc = ks * 8 + tg;
            uint32_t bfr[4][2];
            #pragma unroll
            for (int nt = 0; nt < 4; nt++) {
                int nrow = wc * 32 + nt * 8 + g;
                bfr[nt][0] = f2tf32(Bs[nrow * SA + kc]);
                bfr[nt][1] = f2tf32(Bs[nrow * SA + kc + 4]);
            }
            #pragma unroll
            for (int mt = 0; mt < 4; mt++) {
                int ar0 = wr * 64 + mt * 16 + g;
                uint32_t a0 = f2tf32(As[ar0 * SA + kc]);
                uint32_t a1 = f2tf32(As[(ar0 + 8) * SA + kc]);
                uint32_t a2 = f2tf32(As[ar0 * SA + kc + 4]);
                uint32_t a3 = f2tf32(As[(ar0 + 8) * SA + kc + 4]);
                #pragma unroll
                for (int nt = 0; nt < 4; nt++)
                    mma_tf32(acc[mt][nt][0], acc[mt][nt][1], acc[mt][nt][2], acc[mt][nt][3],
                             a0, a1, a2, a3, bfr[nt][0], bfr[nt][1]);
            }
        }

        CP_WAIT(STAGES - 2);
        __syncthreads();
    }

    // ---- epilogue: bias + store ----
    #pragma unroll
    for (int mt = 0; mt < 4; mt++) {
        int r0 = m0 + wr * 64 + mt * 16 + g;
        #pragma unroll
        for (int nt = 0; nt < 4; nt++) {
            int cc = n0 + wc * 32 + nt * 8 + 2 * tg;
            float2 bv = *(const float2*)(bias + cc);
            float2 o0, o1;
            o0.x = acc[mt][nt][0] + bv.x;
            o0.y = acc[mt][nt][1] + bv.y;
            o1.x = acc[mt][nt][2] + bv.x;
            o1.y = acc[mt][nt][3] + bv.y;
            *(float2*)(C + (size_t)r0 * N + cc)       = o0;
            *(float2*)(C + (size_t)(r0 + 8) * N + cc) = o1;
        }
    }
}

// ---------------------------------------------------------------------------
// RoPE in place on X: [B*T, heads, 128].
// ---------------------------------------------------------------------------
__global__ void rope_kernel(float* __restrict__ X, int heads, long total)
{
    long idx = (long)blockIdx.x * blockDim.x + threadIdx.x;
    if (idx >= total) return;
    int d = (int)(idx & 63);
    long rh = idx >> 6;
    long row = rh / heads;
    int t = (int)(row % T_);

    float inv = powf(10000.0f, -(float)d * (1.0f / 64.0f));
    float ang = (float)t * inv;
    float c = cosf(ang), s = sinf(ang);

    float* p = X + rh * HS_;
    float x1 = p[d], x2 = p[d + 64];
    p[d]      = x1 * c - x2 * s;
    p[d + 64] = x2 * c + x1 * s;
}

// ---------------------------------------------------------------------------
// Causal flash attention, fp32 (unchanged passing kernel).
// ---------------------------------------------------------------------------
#define QT 64
#define KT 64
#define SPAD 65

__global__ __launch_bounds__(256) void attn_kernel(
    const float* __restrict__ Q, const float* __restrict__ K,
    const float* __restrict__ V, float* __restrict__ Y)
{
    extern __shared__ float sma[];
    float* Qs = sma;
    float* Ks = Qs + QT * HS_;
    float* Vs = Ks + HS_ * KT;
    float* Ss = Vs + KT * HS_;
    __shared__ float m_s[QT], l_s[QT], alpha_s[QT];

    int tid = threadIdx.x;
    int qt = blockIdx.x, h = blockIdx.y, b = blockIdx.z;
    int kh = h / GROUPS;
    int sRow = tid >> 4;
    int sCol = tid & 15;
    const float scale = 0.08838834764831845f;

    for (int i = tid; i < QT * HS_ / 4; i += 256) {
        int r  = i >> 5;
        int c4 = (i & 31) * 4;
        *(float4*)(Qs + r * HS_ + c4) =
            *(const float4*)(Q + ((size_t)(b * T_ + qt * QT + r) * H_ + h) * HS_ + c4);
    }
    if (tid < QT) { m_s[tid] = -INFINITY; l_s[tid] = 0.f; }

    float acc[4][8];
    #pragma unroll
    for (int i = 0; i < 4; i++)
        #pragma unroll
        for (int j = 0; j < 8; j++) acc[i][j] = 0.f;

    for (int jt = 0; jt <= qt; jt++) {
        __syncthreads();

        for (int i = tid; i < KT * HS_ / 4; i += 256) {
            int r  = i >> 5;
            int c4 = (i & 31) * 4;
            size_t gbase = ((size_t)(b * T_ + jt * KT + r) * KVH_ + kh) * HS_ + c4;
            float4 kv = *(const float4*)(K + gbase);
            Ks[(c4 + 0) * KT + r] = kv.x;
            Ks[(c4 + 1) * KT + r] = kv.y;
            Ks[(c4 + 2) * KT + r] = kv.z;
            Ks[(c4 + 3) * KT + r] = kv.w;
            *(float4*)(Vs + r * HS_ + c4) = *(const float4*)(V + gbase);
        }
        __syncthreads();

        float s44[4][4];
        #pragma unroll
        for (int i = 0; i < 4; i++)
            #pragma unroll
            for (int j = 0; j < 4; j++) s44[i][j] = 0.f;

        #pragma unroll 16
        for (int k = 0; k < HS_; k++) {
            float4 kk = *(float4*)(Ks + k * KT + sCol * 4);
            float q0 = Qs[(sRow * 4 + 0) * HS_ + k];
            float q1 = Qs[(sRow * 4 + 1) * HS_ + k];
            float q2 = Qs[(sRow * 4 + 2) * HS_ + k];
            float q3 = Qs[(sRow * 4 + 3) * HS_ + k];
            s44[0][0] += q0 * kk.x; s44[0][1] += q0 * kk.y; s44[0][2] += q0 * kk.z; s44[0][3] += q0 * kk.w;
            s44[1][0] += q1 * kk.x; s44[1][1] += q1 * kk.y; s44[1][2] += q1 * kk.z; s44[1][3] += q1 * kk.w;
            s44[2][0] += q2 * kk.x; s44[2][1] += q2 * kk.y; s44[2][2] += q2 * kk.z; s44[2][3] += q2 * kk.w;
            s44[3][0] += q3 * kk.x; s44[3][1] += q3 * kk.y; s44[3][2] += q3 * kk.z; s44[3][3] += q3 * kk.w;
        }
        #pragma unroll
        for (int i = 0; i < 4; i++)
            #pragma unroll
            for (int j = 0; j < 4; j++)
                Ss[(sRow * 4 + i) * SPAD + sCol * 4 + j] = s44[i][j] * scale;
        __syncthreads();

        if (tid < QT) {
            int r = tid;
            int jmax = (jt == qt) ? (r + 1) : KT;
            float m_old = m_s[r];
            float mx = m_old;
            for (int j = 0; j < jmax; j++) mx = fmaxf(mx, Ss[r * SPAD + j]);
            float a = expf(m_old - mx);
            float lsum = 0.f;
            for (int j = 0; j < KT; j++) {
                float p = (j < jmax) ? expf(Ss[r * SPAD + j] - mx) : 0.f;
                Ss[r * SPAD + j] = p;
                lsum += p;
            }
            l_s[r] = l_s[r] * a + lsum;
            m_s[r] = mx;
            alpha_s[r] = a;
        }
        __syncthreads();

        #pragma unroll
        for (int i = 0; i < 4; i++) {
            float a = alpha_s[sRow * 4 + i];
            #pragma unroll
            for (int j = 0; j < 8; j++) acc[i][j] *= a;
        }
        #pragma unroll 8
        for (int j = 0; j < KT; j++) {
            float4 v0 = *(float4*)(Vs + j * HS_ + sCol * 8);
            float4 v1 = *(float4*)(Vs + j * HS_ + sCol * 8 + 4);
            #pragma unroll
            for (int i = 0; i < 4; i++) {
                float p = Ss[(sRow * 4 + i) * SPAD + j];
                acc[i][0] += p * v0.x; acc[i][1] += p * v0.y;
                acc[i][2] += p * v0.z; acc[i][3] += p * v0.w;
                acc[i][4] += p * v1.x; acc[i][5] += p * v1.y;
                acc[i][6] += p * v1.z; acc[i][7] += p * v1.w;
            }
        }
    }

    #pragma unroll
    for (int i = 0; i < 4; i++) {
        int r = sRow * 4 + i;
        float inv_l = 1.f / l_s[r];
        float4 o0, o1;
        o0.x = acc[i][0] * inv_l; o0.y = acc[i][1] * inv_l;
        o0.z = acc[i][2] * inv_l; o0.w = acc[i][3] * inv_l;
        o1.x = acc[i][4] * inv_l; o1.y = acc[i][5] * inv_l;
        o1.z = acc[i][6] * inv_l; o1.w = acc[i][7] * inv_l;
        size_t base = (size_t)(b * T_ + qt * QT + r) * (H_ * HS_) + h * HS_ + sCol * 8;
        *(float4*)(Y + base)     = o0;
        *(float4*)(Y + base + 4) = o1;
    }
}

// ---------------------------------------------------------------------------
extern "C" void kernel_launch(void* const* d_in, const int* in_sizes, int n_in,
                              void* d_out, int out_size)
{
    const float* q_x  = (const float*)d_in[0];
    const float* kv_x = (const float*)d_in[1];
    const float* Wq   = (const float*)d_in[2];
    const float* bq   = (const float*)d_in[3];
    const float* Wk   = (const float*)d_in[4];
    const float* bk   = (const float*)d_in[5];
    const float* Wv   = (const float*)d_in[6];
    const float* bv   = (const float*)d_in[7];
    const float* Wo   = (const float*)d_in[8];
    const float* bo   = (const float*)d_in[9];
    float* out = (float*)d_out;

    float *qp, *kp, *vp, *yp, *wqT, *wkT, *wvT, *woT;
    cudaGetSymbolAddress((void**)&qp, g_Q);
    cudaGetSymbolAddress((void**)&kp, g_K);
    cudaGetSymbolAddress((void**)&vp, g_V);
    cudaGetSymbolAddress((void**)&yp, g_Y);
    cudaGetSymbolAddress((void**)&wqT, g_WqT);
    cudaGetSymbolAddress((void**)&wkT, g_WkT);
    cudaGetSymbolAddress((void**)&wvT, g_WvT);
    cudaGetSymbolAddress((void**)&woT, g_WoT);

    const int M = B_ * T_;          // 4096
    const int NQ = H_ * HS_;        // 4096
    const int NKV = KVH_ * HS_;     // 1024

    // Weight transposes: W[K,N] -> WT[N,K]
    dim3 tb(32, 8);
    transpose_kernel<<<dim3(NQ / 32, C_ / 32), tb>>>(Wq, wqT, C_, NQ);
    transpose_kernel<<<dim3(NKV / 32, C_ / 32), tb>>>(Wk, wkT, C_, NKV);
    transpose_kernel<<<dim3(NKV / 32, C_ / 32), tb>>>(Wv, wvT, C_, NKV);
    transpose_kernel<<<dim3(C_ / 32, NQ / 32), tb>>>(Wo, woT, NQ, C_);

    cudaFuncSetAttribute(mma_gemm_bias, cudaFuncAttributeMaxDynamicSharedMemorySize, GEMM_SMEM);

    // Projections (tf32 mma.sync)
    mma_gemm_bias<<<dim3(NQ / 128, M / 128), 256, GEMM_SMEM>>>(NQ, q_x, wqT, bq, qp);
    mma_gemm_bias<<<dim3(NKV / 128, M / 128), 256, GEMM_SMEM>>>(NKV, kv_x, wkT, bk, kp);
    mma_gemm_bias<<<dim3(NKV / 128, M / 128), 256, GEMM_SMEM>>>(NKV, kv_x, wvT, bv, vp);

    // RoPE
    long tq = (long)B_ * T_ * H_ * 64;
    long tk = (long)B_ * T_ * KVH_ * 64;
    rope_kernel<<<(unsigned)((tq + 255) / 256), 256>>>(qp, H_, tq);
    rope_kernel<<<(unsigned)((tk + 255) / 256), 256>>>(kp, KVH_, tk);

    // Attention
    size_t smem = (size_t)(QT * HS_ + HS_ * KT + KT * HS_ + QT * SPAD) * sizeof(float);
    cudaFuncSetAttribute(attn_kernel, cudaFuncAttributeMaxDynamicSharedMemorySize, (int)smem);
    attn_kernel<<<dim3(T_ / QT, H_, B_), 256, smem>>>(qp, kp, vp, yp);

    // Output projection (tf32 mma.sync)
    mma_gemm_bias<<<dim3(C_ / 128, M / 128), 256, GEMM_SMEM>>>(C_, yp, woT, bo, out);
}

// round 4
// speedup vs baseline: 3.9532x; 1.9918x over previous
#include <cuda_runtime.h>
#include <math.h>
#include <cstdint>

#define B_   2
#define T_   2048
#define C_   4096
#define H_   32
#define KVH_ 8
#define HS_  128
#define GROUPS (H_/KVH_)
#define GK    4096

// ---------------------------------------------------------------------------
// Scratch
// ---------------------------------------------------------------------------
__device__ float g_Q[(size_t)B_*T_*H_*HS_];
__device__ float g_K[(size_t)B_*T_*KVH_*HS_];
__device__ float g_V[(size_t)B_*T_*KVH_*HS_];
__device__ float g_Y[(size_t)B_*T_*H_*HS_];
__device__ float g_WqT[(size_t)C_*H_*HS_];
__device__ float g_WkT[(size_t)C_*KVH_*HS_];
__device__ float g_WvT[(size_t)C_*KVH_*HS_];
__device__ float g_WoT[(size_t)H_*HS_*C_];
__device__ float g_Xq[(size_t)B_*T_*C_];     // tf32-rounded q_x
__device__ float g_Xkv[(size_t)B_*T_*C_];    // tf32-rounded kv_x

// ---------------------------------------------------------------------------
// Helpers
// ---------------------------------------------------------------------------
__device__ __forceinline__ uint32_t smem_to_u32(const void* p) {
    uint32_t a;
    asm("{ .reg .u64 t; cvta.to.shared.u64 t, %1; cvt.u32.u64 %0, t; }" : "=r"(a) : "l"(p));
    return a;
}
__device__ __forceinline__ uint32_t f2tf32(float x) {
    uint32_t u;
    asm("cvt.rna.tf32.f32 %0, %1;" : "=r"(u) : "f"(x));
    return u;
}
__device__ __forceinline__ float rndf(float x) { return __uint_as_float(f2tf32(x)); }

__device__ __forceinline__ void cp_async16(uint32_t smem_addr, const void* gptr) {
    asm volatile("cp.async.cg.shared.global [%0], [%1], 16;" :: "r"(smem_addr), "l"(gptr));
}
#define CP_COMMIT() asm volatile("cp.async.commit_group;" ::: "memory")
#define CP_WAIT(n)  asm volatile("cp.async.wait_group %0;" :: "n"(n) : "memory")

__device__ __forceinline__ void mma_tf32(
    float& d0, float& d1, float& d2, float& d3,
    uint32_t a0, uint32_t a1, uint32_t a2, uint32_t a3,
    uint32_t b0, uint32_t b1)
{
    asm volatile(
        "mma.sync.aligned.m16n8k8.row.col.f32.tf32.tf32.f32 "
        "{%0,%1,%2,%3}, {%4,%5,%6,%7}, {%8,%9}, {%0,%1,%2,%3};"
        : "+f"(d0), "+f"(d1), "+f"(d2), "+f"(d3)
        : "r"(a0), "r"(a1), "r"(a2), "r"(a3), "r"(b0), "r"(b1));
}

// ---------------------------------------------------------------------------
// Launch 1: round both inputs to tf32
// ---------------------------------------------------------------------------
#define N4IN 4194304L   // 4096*4096/4
__global__ void cvt_inputs(const float4* __restrict__ qx, const float4* __restrict__ kvx,
                           float4* __restrict__ oq, float4* __restrict__ okv)
{
    long i = (long)blockIdx.x * blockDim.x + threadIdx.x;
    const float4* s; float4* d; long j;
    if (i < N4IN) { s = qx; d = oq; j = i; }
    else          { s = kvx; d = okv; j = i - N4IN; }
    float4 v = s[j];
    v.x = rndf(v.x); v.y = rndf(v.y); v.z = rndf(v.z); v.w = rndf(v.w);
    d[j] = v;
}

// ---------------------------------------------------------------------------
// Launch 2: fused transpose of all 4 weights, rounding to tf32 on write.
// src [rows][cols] -> dst [cols][rows]
// ---------------------------------------------------------------------------
__global__ void transpose4(const float* __restrict__ Wq, const float* __restrict__ Wk,
                           const float* __restrict__ Wv, const float* __restrict__ Wo,
                           float* __restrict__ wqT, float* __restrict__ wkT,
                           float* __restrict__ wvT, float* __restrict__ woT)
{
    __shared__ float tile[32][33];
    int z = blockIdx.z;
    const float* src; float* dst; int rows, cols;
    if (z == 0)      { src = Wq; dst = wqT; rows = 4096; cols = 4096; }
    else if (z == 1) { src = Wk; dst = wkT; rows = 4096; cols = 1024; if (blockIdx.x >= 32) return; }
    else if (z == 2) { src = Wv; dst = wvT; rows = 4096; cols = 1024; if (blockIdx.x >= 32) return; }
    else             { src = Wo; dst = woT; rows = 4096; cols = 4096; }
    int c0 = blockIdx.x * 32, r0 = blockIdx.y * 32;
    int x = threadIdx.x;
    #pragma unroll
    for (int y = threadIdx.y; y < 32; y += 8)
        tile[y][x] = src[(size_t)(r0 + y) * cols + c0 + x];
    __syncthreads();
    #pragma unroll
    for (int y = threadIdx.y; y < 32; y += 8)
        dst[(size_t)(c0 + y) * rows + r0 + x] = rndf(tile[x][y]);
}

// ---------------------------------------------------------------------------
// tf32 mma.sync GEMM core (operands pre-rounded; no cvt in loop).
// ---------------------------------------------------------------------------
#define SA        36
#define STAGES    4
#define STAGE_FLT (2 * 128 * SA)
#define GEMM_SMEM (STAGES * STAGE_FLT * 4)
#define KTILES    (GK / 32)

__device__ __forceinline__ void gemm_core(
    int N, const float* __restrict__ A, const float* __restrict__ BT,
    const float* __restrict__ bias, float* __restrict__ C,
    int m0, int n0, float* sm)
{
    uint32_t sb = smem_to_u32(sm);
    int tid  = threadIdx.x;
    int lane = tid & 31, wid = tid >> 5;
    int wr = wid >> 2, wc = wid & 3;
    int g  = lane >> 2, tg = lane & 3;
    int ldRow = tid >> 3;
    int ldC4  = (tid & 7) * 4;

    float acc[4][4][4];
    #pragma unroll
    for (int i = 0; i < 4; i++)
        #pragma unroll
        for (int j = 0; j < 4; j++)
            #pragma unroll
            for (int k = 0; k < 4; k++) acc[i][j][k] = 0.f;

    auto issue_tile = [&](int kt, int s) {
        const float* Ag = A  + (size_t)(m0) * GK + kt * 32;
        const float* Bg = BT + (size_t)(n0) * GK + kt * 32;
        uint32_t stA = sb + (uint32_t)(s * STAGE_FLT) * 4;
        uint32_t stB = stA + (uint32_t)(128 * SA) * 4;
        #pragma unroll
        for (int i = 0; i < 4; i++) {
            int row = ldRow + 32 * i;
            uint32_t soff = (uint32_t)(row * SA + ldC4) * 4;
            cp_async16(stA + soff, Ag + (size_t)row * GK + ldC4);
            cp_async16(stB + soff, Bg + (size_t)row * GK + ldC4);
        }
    };

    #pragma unroll
    for (int s = 0; s < STAGES - 1; s++) { issue_tile(s, s); CP_COMMIT(); }
    CP_WAIT(STAGES - 2);
    __syncthreads();

    for (int kt = 0; kt < KTILES; kt++) {
        if (kt + STAGES - 1 < KTILES)
            issue_tile(kt + STAGES - 1, (kt + STAGES - 1) & (STAGES - 1));
        CP_COMMIT();

        const float* As = sm + (kt & (STAGES - 1)) * STAGE_FLT;
        const float* Bs = As + 128 * SA;

        #pragma unroll
        for (int ks = 0; ks < 4; ks++) {
            int kc = ks * 8 + tg;
            uint32_t bfr[4][2];
            #pragma unroll
            for (int nt = 0; nt < 4; nt++) {
                int nrow = wc * 32 + nt * 8 + g;
                bfr[nt][0] = __float_as_uint(Bs[nrow * SA + kc]);
                bfr[nt][1] = __float_as_uint(Bs[nrow * SA + kc + 4]);
            }
            #pragma unroll
            for (int mt = 0; mt < 4; mt++) {
                int ar0 = wr * 64 + mt * 16 + g;
                uint32_t a0 = __float_as_uint(As[ar0 * SA + kc]);
                uint32_t a1 = __float_as_uint(As[(ar0 + 8) * SA + kc]);
                uint32_t a2 = __float_as_uint(As[ar0 * SA + kc + 4]);
                uint32_t a3 = __float_as_uint(As[(ar0 + 8) * SA + kc + 4]);
                #pragma unroll
                for (int nt = 0; nt < 4; nt++)
                    mma_tf32(acc[mt][nt][0], acc[mt][nt][1], acc[mt][nt][2], acc[mt][nt][3],
                             a0, a1, a2, a3, bfr[nt][0], bfr[nt][1]);
            }
        }
        CP_WAIT(STAGES - 2);
        __syncthreads();
    }

    #pragma unroll
    for (int mt = 0; mt < 4; mt++) {
        int r0 = m0 + wr * 64 + mt * 16 + g;
        #pragma unroll
        for (int nt = 0; nt < 4; nt++) {
            int cc = n0 + wc * 32 + nt * 8 + 2 * tg;
            float2 bv = *(const float2*)(bias + cc);
            float2 o0, o1;
            o0.x = acc[mt][nt][0] + bv.x;
            o0.y = acc[mt][nt][1] + bv.y;
            o1.x = acc[mt][nt][2] + bv.x;
            o1.y = acc[mt][nt][3] + bv.y;
            *(float2*)(C + (size_t)r0 * N + cc)       = o0;
            *(float2*)(C + (size_t)(r0 + 8) * N + cc) = o1;
        }
    }
}

// Launch 3: Q projection (and 7: O projection)
__global__ __launch_bounds__(256) void mma_gemm_bias(
    int N, const float* __restrict__ A, const float* __restrict__ BT,
    const float* __restrict__ bias, float* __restrict__ C)
{
    extern __shared__ float sm[];
    gemm_core(N, A, BT, bias, C, blockIdx.y * 128, blockIdx.x * 128, sm);
}

// Launch 4: fused K+V projection (grid.x = 16; first 8 -> K, last 8 -> V)
__global__ __launch_bounds__(256) void mma_gemm_kv(
    const float* __restrict__ A,
    const float* __restrict__ BTk, const float* __restrict__ BTv,
    const float* __restrict__ bk, const float* __restrict__ bv,
    float* __restrict__ Ck, float* __restrict__ Cv)
{
    extern __shared__ float sm[];
    int bx = blockIdx.x;
    if (bx < 8) gemm_core(1024, A, BTk, bk, Ck, blockIdx.y * 128, bx * 128, sm);
    else        gemm_core(1024, A, BTv, bv, Cv, blockIdx.y * 128, (bx - 8) * 128, sm);
}

// ---------------------------------------------------------------------------
// Launch 5: fused RoPE(Q) + RoPE(K) + tf32-round(V). All writes tf32-rounded.
// ---------------------------------------------------------------------------
#define PP_Q  8388608L            // B*T*H*64
#define PP_K  2097152L            // B*T*KVH*64
#define PP_V4 1048576L            // B*T*KVH*128/4
__global__ void postproc(float* __restrict__ Q, float* __restrict__ K, float* __restrict__ V)
{
    long i = (long)blockIdx.x * blockDim.x + threadIdx.x;
    if (i < PP_Q + PP_K) {
        float* X; int heads; long idx;
        if (i < PP_Q) { X = Q; heads = H_; idx = i; }
        else          { X = K; heads = KVH_; idx = i - PP_Q; }
        int d = (int)(idx & 63);
        long rh = idx >> 6;
        long row = rh / heads;
        int t = (int)(row % T_);
        float inv = powf(10000.0f, -(float)d * (1.0f / 64.0f));
        float ang = (float)t * inv;
        float c = cosf(ang), s = sinf(ang);
        float* p = X + rh * HS_;
        float x1 = p[d], x2 = p[d + 64];
        p[d]      = rndf(x1 * c - x2 * s);
        p[d + 64] = rndf(x2 * c + x1 * s);
    } else {
        long j = i - (PP_Q + PP_K);
        float4 v = ((float4*)V)[j];
        v.x = rndf(v.x); v.y = rndf(v.y); v.z = rndf(v.z); v.w = rndf(v.w);
        ((float4*)V)[j] = v;
    }
}

// ---------------------------------------------------------------------------
// Launch 6: tensor-core causal flash attention (tf32 mma.sync).
// 256 threads (8 warps), Q tile 128x128 (Q frags in regs), K/V tiles 64,
// 2-stage cp.async ring, register softmax with quad shuffles.
// Output Y written tf32-rounded (feeds O-proj).
// ---------------------------------------------------------------------------
#define KS_STRIDE 132
#define VS_STRIDE 136
#define PS_STRIDE 68
#define OFF_KS0 0
#define OFF_VS0 8448
#define OFF_KS1 17152
#define OFF_VS1 25600
#define OFF_PS  34304
#define ATTN_SMEM (43008 * 4)

__global__ __launch_bounds__(256) void attn_mma(
    const float* __restrict__ Q, const float* __restrict__ K,
    const float* __restrict__ V, float* __restrict__ Y)
{
    extern __shared__ float sm[];
    uint32_t sb = smem_to_u32(sm);
    int tid = threadIdx.x, lane = tid & 31, w = tid >> 5;
    int g = lane >> 2, tg = lane & 3;
    int qb = blockIdx.x, h = blockIdx.y, b = blockIdx.z;
    int kh = h / GROUPS;
    const float scale = 0.08838834764831845f;
    int r0 = qb * 128 + w * 16 + g;          // global row (thread's first row)

    // ---- stage Q (coalesced) into smem, extract fragments to registers ----
    for (int i = tid; i < 128 * 32; i += 256) {
        int row = i >> 5, c4 = (i & 31) * 4;
        *(float4*)(sm + row * KS_STRIDE + c4) =
            *(const float4*)(Q + (size_t)(b * T_ + qb * 128 + row) * (H_ * HS_) + h * HS_ + c4);
    }
    __syncthreads();
    uint32_t qf[16][4];
    #pragma unroll
    for (int ks = 0; ks < 16; ks++) {
        int kc = ks * 8 + tg;
        qf[ks][0] = f2tf32(sm[(w * 16 + g)     * KS_STRIDE + kc]     * scale);
        qf[ks][1] = f2tf32(sm[(w * 16 + g + 8) * KS_STRIDE + kc]     * scale);
        qf[ks][2] = f2tf32(sm[(w * 16 + g)     * KS_STRIDE + kc + 4] * scale);
        qf[ks][3] = f2tf32(sm[(w * 16 + g + 8) * KS_STRIDE + kc + 4] * scale);
    }
    __syncthreads();

    float O[16][4];
    #pragma unroll
    for (int i = 0; i < 16; i++)
        #pragma unroll
        for (int j = 0; j < 4; j++) O[i][j] = 0.f;
    float m0 = -1e30f, m1 = -1e30f, l0 = 0.f, l1 = 0.f;

    int nt = 2 * qb + 2;

    auto issue_kv = [&](int jt, int s) {
        uint32_t kbase = sb + (uint32_t)(s ? OFF_KS1 : OFF_KS0) * 4;
        uint32_t vbase = sb + (uint32_t)(s ? OFF_VS1 : OFF_VS0) * 4;
        #pragma unroll
        for (int j = 0; j < 8; j++) {
            int ii = tid + 256 * j;
            int row = ii >> 5;
            int c4 = (ii & 31) * 4;
            size_t gidx = ((size_t)(b * T_ + jt * 64 + row) * KVH_ + kh) * HS_ + c4;
            cp_async16(kbase + (uint32_t)(row * KS_STRIDE + c4) * 4, K + gidx);
            cp_async16(vbase + (uint32_t)(row * VS_STRIDE + c4) * 4, V + gidx);
        }
    };

    issue_kv(0, 0);
    CP_COMMIT();

    for (int jt = 0; jt < nt; jt++) {
        if (jt + 1 < nt) issue_kv(jt + 1, (jt + 1) & 1);
        CP_COMMIT();
        CP_WAIT(1);
        __syncthreads();

        const float* Ksm = sm + ((jt & 1) ? OFF_KS1 : OFF_KS0);
        const float* Vsm = sm + ((jt & 1) ? OFF_VS1 : OFF_VS0);

        // ---- S = Q K^T (scaled) ----
        float S[8][4];
        #pragma unroll
        for (int i = 0; i < 8; i++)
            #pragma unroll
            for (int j = 0; j < 4; j++) S[i][j] = 0.f;

        #pragma unroll
        for (int ks = 0; ks < 16; ks++) {
            int kc = ks * 8 + tg;
            #pragma unroll
            for (int nf = 0; nf < 8; nf++) {
                uint32_t b0 = __float_as_uint(Ksm[(nf * 8 + g) * KS_STRIDE + kc]);
                uint32_t b1 = __float_as_uint(Ksm[(nf * 8 + g) * KS_STRIDE + kc + 4]);
                mma_tf32(S[nf][0], S[nf][1], S[nf][2], S[nf][3],
                         qf[ks][0], qf[ks][1], qf[ks][2], qf[ks][3], b0, b1);
            }
        }

        // ---- causal mask (only diagonal tiles) ----
        if (jt >= 2 * qb) {
            int cb = jt * 64;
            #pragma unroll
            for (int nf = 0; nf < 8; nf++) {
                int c0 = cb + nf * 8 + 2 * tg, c1 = c0 + 1;
                if (c0 > r0)     S[nf][0] = -1e30f;
                if (c1 > r0)     S[nf][1] = -1e30f;
                if (c0 > r0 + 8) S[nf][2] = -1e30f;
                if (c1 > r0 + 8) S[nf][3] = -1e30f;
            }
        }

        // ---- online softmax (registers + quad shuffles) ----
        float mx0 = -1e30f, mx1 = -1e30f;
        #pragma unroll
        for (int nf = 0; nf < 8; nf++) {
            mx0 = fmaxf(mx0, fmaxf(S[nf][0], S[nf][1]));
            mx1 = fmaxf(mx1, fmaxf(S[nf][2], S[nf][3]));
        }
        mx0 = fmaxf(mx0, __shfl_xor_sync(0xffffffffu, mx0, 1));
        mx0 = fmaxf(mx0, __shfl_xor_sync(0xffffffffu, mx0, 2));
        mx1 = fmaxf(mx1, __shfl_xor_sync(0xffffffffu, mx1, 1));
        mx1 = fmaxf(mx1, __shfl_xor_sync(0xffffffffu, mx1, 2));

        float mn0 = fmaxf(m0, mx0), mn1 = fmaxf(m1, mx1);
        float a0 = __expf(m0 - mn0), a1 = __expf(m1 - mn1);
        float s0 = 0.f, s1 = 0.f;
        #pragma unroll
        for (int nf = 0; nf < 8; nf++) {
            S[nf][0] = __expf(S[nf][0] - mn0);
            S[nf][1] = __expf(S[nf][1] - mn0);
            S[nf][2] = __expf(S[nf][2] - mn1);
            S[nf][3] = __expf(S[nf][3] - mn1);
            s0 += S[nf][0] + S[nf][1];
            s1 += S[nf][2] + S[nf][3];
        }
        s0 += __shfl_xor_sync(0xffffffffu, s0, 1);
        s0 += __shfl_xor_sync(0xffffffffu, s0, 2);
        s1 += __shfl_xor_sync(0xffffffffu, s1, 1);
        s1 += __shfl_xor_sync(0xffffffffu, s1, 2);
        l0 = l0 * a0 + s0; l1 = l1 * a1 + s1;
        m0 = mn0; m1 = mn1;

        #pragma unroll
        for (int nf2 = 0; nf2 < 16; nf2++) {
            O[nf2][0] *= a0; O[nf2][1] *= a0;
            O[nf2][2] *= a1; O[nf2][3] *= a1;
        }

        // ---- stage P (tf32) into per-warp smem region ----
        float* Psm = sm + OFF_PS;
        int prow0 = (w * 16 + g) * PS_STRIDE;
        int prow1 = (w * 16 + g + 8) * PS_STRIDE;
        #pragma unroll
        for (int nf = 0; nf < 8; nf++) {
            *(float2*)(Psm + prow0 + nf * 8 + 2 * tg) = make_float2(rndf(S[nf][0]), rndf(S[nf][1]));
            *(float2*)(Psm + prow1 + nf * 8 + 2 * tg) = make_float2(rndf(S[nf][2]), rndf(S[nf][3]));
        }
        __syncwarp();

        // ---- O += P V ----
        #pragma unroll
        for (int ks2 = 0; ks2 < 8; ks2++) {
            int kc2 = ks2 * 8 + tg;
            uint32_t pa0 = __float_as_uint(Psm[prow0 + kc2]);
            uint32_t pa1 = __float_as_uint(Psm[prow1 + kc2]);
            uint32_t pa2 = __float_as_uint(Psm[prow0 + kc2 + 4]);
            uint32_t pa3 = __float_as_uint(Psm[prow1 + kc2 + 4]);
            #pragma unroll
            for (int nf2 = 0; nf2 < 16; nf2++) {
                uint32_t b0 = __float_as_uint(Vsm[kc2 * VS_STRIDE + nf2 * 8 + g]);
                uint32_t b1 = __float_as_uint(Vsm[(kc2 + 4) * VS_STRIDE + nf2 * 8 + g]);
                mma_tf32(O[nf2][0], O[nf2][1], O[nf2][2], O[nf2][3],
                         pa0, pa1, pa2, pa3, b0, b1);
            }
        }
        __syncthreads();
    }

    // ---- epilogue: normalize, round to tf32, store ----
    float il0 = 1.f / l0, il1 = 1.f / l1;
    size_t base0 = (size_t)(b * T_ + r0) * (H_ * HS_) + h * HS_;
    size_t base1 = base0 + (size_t)8 * (H_ * HS_);
    #pragma unroll
    for (int nf2 = 0; nf2 < 16; nf2++) {
        *(float2*)(Y + base0 + nf2 * 8 + 2 * tg) =
            make_float2(rndf(O[nf2][0] * il0), rndf(O[nf2][1] * il0));
        *(float2*)(Y + base1 + nf2 * 8 + 2 * tg) =
            make_float2(rndf(O[nf2][2] * il1), rndf(O[nf2][3] * il1));
    }
}

// ---------------------------------------------------------------------------
extern "C" void kernel_launch(void* const* d_in, const int* in_sizes, int n_in,
                              void* d_out, int out_size)
{
    const float* q_x  = (const float*)d_in[0];
    const float* kv_x = (const float*)d_in[1];
    const float* Wq   = (const float*)d_in[2];
    const float* bq   = (const float*)d_in[3];
    const float* Wk   = (const float*)d_in[4];
    const float* bk   = (const float*)d_in[5];
    const float* Wv   = (const float*)d_in[6];
    const float* bv   = (const float*)d_in[7];
    const float* Wo   = (const float*)d_in[8];
    const float* bo   = (const float*)d_in[9];
    float* out = (float*)d_out;

    float *qp, *kp, *vp, *yp, *wqT, *wkT, *wvT, *woT, *xq, *xkv;
    cudaGetSymbolAddress((void**)&qp, g_Q);
    cudaGetSymbolAddress((void**)&kp, g_K);
    cudaGetSymbolAddress((void**)&vp, g_V);
    cudaGetSymbolAddress((void**)&yp, g_Y);
    cudaGetSymbolAddress((void**)&wqT, g_WqT);
    cudaGetSymbolAddress((void**)&wkT, g_WkT);
    cudaGetSymbolAddress((void**)&wvT, g_WvT);
    cudaGetSymbolAddress((void**)&woT, g_WoT);
    cudaGetSymbolAddress((void**)&xq, g_Xq);
    cudaGetSymbolAddress((void**)&xkv, g_Xkv);

    const int M = B_ * T_;          // 4096
    const int NQ = H_ * HS_;        // 4096

    cudaFuncSetAttribute(mma_gemm_bias, cudaFuncAttributeMaxDynamicSharedMemorySize, GEMM_SMEM);
    cudaFuncSetAttribute(mma_gemm_kv, cudaFuncAttributeMaxDynamicSharedMemorySize, GEMM_SMEM);
    cudaFuncSetAttribute(attn_mma, cudaFuncAttributeMaxDynamicSharedMemorySize, ATTN_SMEM);

    // 1. round inputs to tf32
    cvt_inputs<<<(unsigned)(2 * N4IN / 256), 256>>>((const float4*)q_x, (const float4*)kv_x,
                                                    (float4*)xq, (float4*)xkv);
    // 2. transpose + round all weights
    transpose4<<<dim3(128, 128, 4), dim3(32, 8)>>>(Wq, Wk, Wv, Wo, wqT, wkT, wvT, woT);
    // 3. Q projection
    mma_gemm_bias<<<dim3(NQ / 128, M / 128), 256, GEMM_SMEM>>>(NQ, xq, wqT, bq, qp);
    // 4. fused K+V projection
    mma_gemm_kv<<<dim3(16, M / 128), 256, GEMM_SMEM>>>(xkv, wkT, wvT, bk, bv, kp, vp);
    // 5. RoPE(Q,K) + round(V)
    postproc<<<(unsigned)((PP_Q + PP_K + PP_V4) / 256), 256>>>(qp, kp, vp);
    // 6. attention
    attn_mma<<<dim3(T_ / 128, H_, B_), 256, ATTN_SMEM>>>(qp, kp, vp, yp);
    // 7. output projection
    mma_gemm_bias<<<dim3(C_ / 128, M / 128), 256, GEMM_SMEM>>>(C_, yp, woT, bo, out);
}

// round 5
// speedup vs baseline: 4.5674x; 1.1554x over previous
#include <cuda_runtime.h>
#include <math.h>
#include <cstdint>

#define B_   2
#define T_   2048
#define C_   4096
#define H_   32
#define KVH_ 8
#define HS_  128
#define GROUPS (H_/KVH_)
#define GK    4096

// ---------------------------------------------------------------------------
// Scratch
// ---------------------------------------------------------------------------
__device__ float g_Q[(size_t)B_*T_*H_*HS_];
__device__ float g_K[(size_t)B_*T_*KVH_*HS_];
__device__ float g_V[(size_t)B_*T_*KVH_*HS_];
__device__ float g_Y[(size_t)B_*T_*H_*HS_];
__device__ float g_WqT[(size_t)C_*H_*HS_];
__device__ float g_WkT[(size_t)C_*KVH_*HS_];
__device__ float g_WvT[(size_t)C_*KVH_*HS_];
__device__ float g_WoT[(size_t)H_*HS_*C_];
__device__ float g_Xq[(size_t)B_*T_*C_];     // tf32-rounded q_x
__device__ float g_Xkv[(size_t)B_*T_*C_];    // tf32-rounded kv_x

// ---------------------------------------------------------------------------
// Helpers
// ---------------------------------------------------------------------------
__device__ __forceinline__ uint32_t smem_to_u32(const void* p) {
    uint32_t a;
    asm("{ .reg .u64 t; cvta.to.shared.u64 t, %1; cvt.u32.u64 %0, t; }" : "=r"(a) : "l"(p));
    return a;
}
__device__ __forceinline__ uint32_t f2tf32(float x) {
    uint32_t u;
    asm("cvt.rna.tf32.f32 %0, %1;" : "=r"(u) : "f"(x));
    return u;
}
__device__ __forceinline__ float rndf(float x) { return __uint_as_float(f2tf32(x)); }

__device__ __forceinline__ void cp_async16(uint32_t smem_addr, const void* gptr) {
    asm volatile("cp.async.cg.shared.global [%0], [%1], 16;" :: "r"(smem_addr), "l"(gptr));
}
#define CP_COMMIT() asm volatile("cp.async.commit_group;" ::: "memory")
#define CP_WAIT(n)  asm volatile("cp.async.wait_group %0;" :: "n"(n) : "memory")

__device__ __forceinline__ void mma_tf32(
    float& d0, float& d1, float& d2, float& d3,
    uint32_t a0, uint32_t a1, uint32_t a2, uint32_t a3,
    uint32_t b0, uint32_t b1)
{
    asm volatile(
        "mma.sync.aligned.m16n8k8.row.col.f32.tf32.tf32.f32 "
        "{%0,%1,%2,%3}, {%4,%5,%6,%7}, {%8,%9}, {%0,%1,%2,%3};"
        : "+f"(d0), "+f"(d1), "+f"(d2), "+f"(d3)
        : "r"(a0), "r"(a1), "r"(a2), "r"(a3), "r"(b0), "r"(b1));
}

// ---------------------------------------------------------------------------
// Launch 1: round both inputs to tf32
// ---------------------------------------------------------------------------
#define N4IN 4194304L   // 4096*4096/4
__global__ void cvt_inputs(const float4* __restrict__ qx, const float4* __restrict__ kvx,
                           float4* __restrict__ oq, float4* __restrict__ okv)
{
    long i = (long)blockIdx.x * blockDim.x + threadIdx.x;
    const float4* s; float4* d; long j;
    if (i < N4IN) { s = qx; d = oq; j = i; }
    else          { s = kvx; d = okv; j = i - N4IN; }
    float4 v = s[j];
    v.x = rndf(v.x); v.y = rndf(v.y); v.z = rndf(v.z); v.w = rndf(v.w);
    d[j] = v;
}

// ---------------------------------------------------------------------------
// Launch 2: fused transpose of all 4 weights, rounding to tf32 on write.
// ---------------------------------------------------------------------------
__global__ void transpose4(const float* __restrict__ Wq, const float* __restrict__ Wk,
                           const float* __restrict__ Wv, const float* __restrict__ Wo,
                           float* __restrict__ wqT, float* __restrict__ wkT,
                           float* __restrict__ wvT, float* __restrict__ woT)
{
    __shared__ float tile[32][33];
    int z = blockIdx.z;
    const float* src; float* dst; int rows, cols;
    if (z == 0)      { src = Wq; dst = wqT; rows = 4096; cols = 4096; }
    else if (z == 1) { src = Wk; dst = wkT; rows = 4096; cols = 1024; if (blockIdx.x >= 32) return; }
    else if (z == 2) { src = Wv; dst = wvT; rows = 4096; cols = 1024; if (blockIdx.x >= 32) return; }
    else             { src = Wo; dst = woT; rows = 4096; cols = 4096; }
    int c0 = blockIdx.x * 32, r0 = blockIdx.y * 32;
    int x = threadIdx.x;
    #pragma unroll
    for (int y = threadIdx.y; y < 32; y += 8)
        tile[y][x] = src[(size_t)(r0 + y) * cols + c0 + x];
    __syncthreads();
    #pragma unroll
    for (int y = threadIdx.y; y < 32; y += 8)
        dst[(size_t)(c0 + y) * rows + r0 + x] = rndf(tile[x][y]);
}

// ---------------------------------------------------------------------------
// tf32 mma.sync GEMM core. 3-stage ring (110.6 KB) -> 2 CTAs/SM.
// ---------------------------------------------------------------------------
#define SA        36
#define STAGES    3
#define STAGE_FLT (2 * 128 * SA)
#define GEMM_SMEM (STAGES * STAGE_FLT * 4)
#define KTILES    (GK / 32)

__device__ __forceinline__ void gemm_core(
    int N, const float* __restrict__ A, const float* __restrict__ BT,
    const float* __restrict__ bias, float* __restrict__ C,
    int m0, int n0, float* sm)
{
    uint32_t sb = smem_to_u32(sm);
    int tid  = threadIdx.x;
    int lane = tid & 31, wid = tid >> 5;
    int wr = wid >> 2, wc = wid & 3;
    int g  = lane >> 2, tg = lane & 3;
    int ldRow = tid >> 3;
    int ldC4  = (tid & 7) * 4;

    float acc[4][4][4];
    #pragma unroll
    for (int i = 0; i < 4; i++)
        #pragma unroll
        for (int j = 0; j < 4; j++)
            #pragma unroll
            for (int k = 0; k < 4; k++) acc[i][j][k] = 0.f;

    auto issue_tile = [&](int kt, int s) {
        const float* Ag = A  + (size_t)(m0) * GK + kt * 32;
        const float* Bg = BT + (size_t)(n0) * GK + kt * 32;
        uint32_t stA = sb + (uint32_t)(s * STAGE_FLT) * 4;
        uint32_t stB = stA + (uint32_t)(128 * SA) * 4;
        #pragma unroll
        for (int i = 0; i < 4; i++) {
            int row = ldRow + 32 * i;
            uint32_t soff = (uint32_t)(row * SA + ldC4) * 4;
            cp_async16(stA + soff, Ag + (size_t)row * GK + ldC4);
            cp_async16(stB + soff, Bg + (size_t)row * GK + ldC4);
        }
    };

    #pragma unroll
    for (int s = 0; s < STAGES - 1; s++) { issue_tile(s, s); CP_COMMIT(); }
    CP_WAIT(STAGES - 2);
    __syncthreads();

    int stage = 0;
    for (int kt = 0; kt < KTILES; kt++) {
        if (kt + STAGES - 1 < KTILES) {
            int ps = stage + (STAGES - 1);
            if (ps >= STAGES) ps -= STAGES;
            issue_tile(kt + STAGES - 1, ps);
        }
        CP_COMMIT();

        const float* As = sm + stage * STAGE_FLT;
        const float* Bs = As + 128 * SA;

        #pragma unroll
        for (int ks = 0; ks < 4; ks++) {
            int kc = ks * 8 + tg;
            uint32_t bfr[4][2];
            #pragma unroll
            for (int nt = 0; nt < 4; nt++) {
                int nrow = wc * 32 + nt * 8 + g;
                bfr[nt][0] = __float_as_uint(Bs[nrow * SA + kc]);
                bfr[nt][1] = __float_as_uint(Bs[nrow * SA + kc + 4]);
            }
            #pragma unroll
            for (int mt = 0; mt < 4; mt++) {
                int ar0 = wr * 64 + mt * 16 + g;
                uint32_t a0 = __float_as_uint(As[ar0 * SA + kc]);
                uint32_t a1 = __float_as_uint(As[(ar0 + 8) * SA + kc]);
                uint32_t a2 = __float_as_uint(As[ar0 * SA + kc + 4]);
                uint32_t a3 = __float_as_uint(As[(ar0 + 8) * SA + kc + 4]);
                #pragma unroll
                for (int nt = 0; nt < 4; nt++)
                    mma_tf32(acc[mt][nt][0], acc[mt][nt][1], acc[mt][nt][2], acc[mt][nt][3],
                             a0, a1, a2, a3, bfr[nt][0], bfr[nt][1]);
            }
        }
        CP_WAIT(STAGES - 2);
        __syncthreads();
        if (++stage == STAGES) stage = 0;
    }

    #pragma unroll
    for (int mt = 0; mt < 4; mt++) {
        int r0 = m0 + wr * 64 + mt * 16 + g;
        #pragma unroll
        for (int nt = 0; nt < 4; nt++) {
            int cc = n0 + wc * 32 + nt * 8 + 2 * tg;
            float2 bv = *(const float2*)(bias + cc);
            float2 o0, o1;
            o0.x = acc[mt][nt][0] + bv.x;
            o0.y = acc[mt][nt][1] + bv.y;
            o1.x = acc[mt][nt][2] + bv.x;
            o1.y = acc[mt][nt][3] + bv.y;
            *(float2*)(C + (size_t)r0 * N + cc)       = o0;
            *(float2*)(C + (size_t)(r0 + 8) * N + cc) = o1;
        }
    }
}

// Launch 3: Q projection (and 7: O projection)
__global__ __launch_bounds__(256, 2) void mma_gemm_bias(
    int N, const float* __restrict__ A, const float* __restrict__ BT,
    const float* __restrict__ bias, float* __restrict__ C)
{
    extern __shared__ float sm[];
    gemm_core(N, A, BT, bias, C, blockIdx.y * 128, blockIdx.x * 128, sm);
}

// Launch 4: fused K+V projection
__global__ __launch_bounds__(256, 2) void mma_gemm_kv(
    const float* __restrict__ A,
    const float* __restrict__ BTk, const float* __restrict__ BTv,
    const float* __restrict__ bk, const float* __restrict__ bv,
    float* __restrict__ Ck, float* __restrict__ Cv)
{
    extern __shared__ float sm[];
    int bx = blockIdx.x;
    if (bx < 8) gemm_core(1024, A, BTk, bk, Ck, blockIdx.y * 128, bx * 128, sm);
    else        gemm_core(1024, A, BTv, bv, Cv, blockIdx.y * 128, (bx - 8) * 128, sm);
}

// ---------------------------------------------------------------------------
// Launch 5: fused RoPE(Q) + RoPE(K) + tf32-round(V).
// ---------------------------------------------------------------------------
#define PP_Q  8388608L
#define PP_K  2097152L
#define PP_V4 1048576L
__global__ void postproc(float* __restrict__ Q, float* __restrict__ K, float* __restrict__ V)
{
    long i = (long)blockIdx.x * blockDim.x + threadIdx.x;
    if (i < PP_Q + PP_K) {
        float* X; int heads; long idx;
        if (i < PP_Q) { X = Q; heads = H_; idx = i; }
        else          { X = K; heads = KVH_; idx = i - PP_Q; }
        int d = (int)(idx & 63);
        long rh = idx >> 6;
        long row = rh / heads;
        int t = (int)(row % T_);
        float inv = powf(10000.0f, -(float)d * (1.0f / 64.0f));
        float ang = (float)t * inv;
        float c = cosf(ang), s = sinf(ang);
        float* p = X + rh * HS_;
        float x1 = p[d], x2 = p[d + 64];
        p[d]      = rndf(x1 * c - x2 * s);
        p[d + 64] = rndf(x2 * c + x1 * s);
    } else {
        long j = i - (PP_Q + PP_K);
        float4 v = ((float4*)V)[j];
        v.x = rndf(v.x); v.y = rndf(v.y); v.z = rndf(v.z); v.w = rndf(v.w);
        ((float4*)V)[j] = v;
    }
}

// ---------------------------------------------------------------------------
// Launch 6: tensor-core causal flash attention (tf32 mma.sync). Unchanged.
// ---------------------------------------------------------------------------
#define KS_STRIDE 132
#define VS_STRIDE 136
#define PS_STRIDE 68
#define OFF_KS0 0
#define OFF_VS0 8448
#define OFF_KS1 17152
#define OFF_VS1 25600
#define OFF_PS  34304
#define ATTN_SMEM (43008 * 4)

__global__ __launch_bounds__(256) void attn_mma(
    const float* __restrict__ Q, const float* __restrict__ K,
    const float* __restrict__ V, float* __restrict__ Y)
{
    extern __shared__ float sm[];
    uint32_t sb = smem_to_u32(sm);
    int tid = threadIdx.x, lane = tid & 31, w = tid >> 5;
    int g = lane >> 2, tg = lane & 3;
    int qb = blockIdx.x, h = blockIdx.y, b = blockIdx.z;
    int kh = h / GROUPS;
    const float scale = 0.08838834764831845f;
    int r0 = qb * 128 + w * 16 + g;

    for (int i = tid; i < 128 * 32; i += 256) {
        int row = i >> 5, c4 = (i & 31) * 4;
        *(float4*)(sm + row * KS_STRIDE + c4) =
            *(const float4*)(Q + (size_t)(b * T_ + qb * 128 + row) * (H_ * HS_) + h * HS_ + c4);
    }
    __syncthreads();
    uint32_t qf[16][4];
    #pragma unroll
    for (int ks = 0; ks < 16; ks++) {
        int kc = ks * 8 + tg;
        qf[ks][0] = f2tf32(sm[(w * 16 + g)     * KS_STRIDE + kc]     * scale);
        qf[ks][1] = f2tf32(sm[(w * 16 + g + 8) * KS_STRIDE + kc]     * scale);
        qf[ks][2] = f2tf32(sm[(w * 16 + g)     * KS_STRIDE + kc + 4] * scale);
        qf[ks][3] = f2tf32(sm[(w * 16 + g + 8) * KS_STRIDE + kc + 4] * scale);
    }
    __syncthreads();

    float O[16][4];
    #pragma unroll
    for (int i = 0; i < 16; i++)
        #pragma unroll
        for (int j = 0; j < 4; j++) O[i][j] = 0.f;
    float m0 = -1e30f, m1 = -1e30f, l0 = 0.f, l1 = 0.f;

    int nt = 2 * qb + 2;

    auto issue_kv = [&](int jt, int s) {
        uint32_t kbase = sb + (uint32_t)(s ? OFF_KS1 : OFF_KS0) * 4;
        uint32_t vbase = sb + (uint32_t)(s ? OFF_VS1 : OFF_VS0) * 4;
        #pragma unroll
        for (int j = 0; j < 8; j++) {
            int ii = tid + 256 * j;
            int row = ii >> 5;
            int c4 = (ii & 31) * 4;
            size_t gidx = ((size_t)(b * T_ + jt * 64 + row) * KVH_ + kh) * HS_ + c4;
            cp_async16(kbase + (uint32_t)(row * KS_STRIDE + c4) * 4, K + gidx);
            cp_async16(vbase + (uint32_t)(row * VS_STRIDE + c4) * 4, V + gidx);
        }
    };

    issue_kv(0, 0);
    CP_COMMIT();

    for (int jt = 0; jt < nt; jt++) {
        if (jt + 1 < nt) issue_kv(jt + 1, (jt + 1) & 1);
        CP_COMMIT();
        CP_WAIT(1);
        __syncthreads();

        const float* Ksm = sm + ((jt & 1) ? OFF_KS1 : OFF_KS0);
        const float* Vsm = sm + ((jt & 1) ? OFF_VS1 : OFF_VS0);

        float S[8][4];
        #pragma unroll
        for (int i = 0; i < 8; i++)
            #pragma unroll
            for (int j = 0; j < 4; j++) S[i][j] = 0.f;

        #pragma unroll
        for (int ks = 0; ks < 16; ks++) {
            int kc = ks * 8 + tg;
            #pragma unroll
            for (int nf = 0; nf < 8; nf++) {
                uint32_t b0 = __float_as_uint(Ksm[(nf * 8 + g) * KS_STRIDE + kc]);
                uint32_t b1 = __float_as_uint(Ksm[(nf * 8 + g) * KS_STRIDE + kc + 4]);
                mma_tf32(S[nf][0], S[nf][1], S[nf][2], S[nf][3],
                         qf[ks][0], qf[ks][1], qf[ks][2], qf[ks][3], b0, b1);
            }
        }

        if (jt >= 2 * qb) {
            int cb = jt * 64;
            #pragma unroll
            for (int nf = 0; nf < 8; nf++) {
                int c0 = cb + nf * 8 + 2 * tg, c1 = c0 + 1;
                if (c0 > r0)     S[nf][0] = -1e30f;
                if (c1 > r0)     S[nf][1] = -1e30f;
                if (c0 > r0 + 8) S[nf][2] = -1e30f;
                if (c1 > r0 + 8) S[nf][3] = -1e30f;
            }
        }

        float mx0 = -1e30f, mx1 = -1e30f;
        #pragma unroll
        for (int nf = 0; nf < 8; nf++) {
            mx0 = fmaxf(mx0, fmaxf(S[nf][0], S[nf][1]));
            mx1 = fmaxf(mx1, fmaxf(S[nf][2], S[nf][3]));
        }
        mx0 = fmaxf(mx0, __shfl_xor_sync(0xffffffffu, mx0, 1));
        mx0 = fmaxf(mx0, __shfl_xor_sync(0xffffffffu, mx0, 2));
        mx1 = fmaxf(mx1, __shfl_xor_sync(0xffffffffu, mx1, 1));
        mx1 = fmaxf(mx1, __shfl_xor_sync(0xffffffffu, mx1, 2));

        float mn0 = fmaxf(m0, mx0), mn1 = fmaxf(m1, mx1);
        float a0 = __expf(m0 - mn0), a1 = __expf(m1 - mn1);
        float s0 = 0.f, s1 = 0.f;
        #pragma unroll
        for (int nf = 0; nf < 8; nf++) {
            S[nf][0] = __expf(S[nf][0] - mn0);
            S[nf][1] = __expf(S[nf][1] - mn0);
            S[nf][2] = __expf(S[nf][2] - mn1);
            S[nf][3] = __expf(S[nf][3] - mn1);
            s0 += S[nf][0] + S[nf][1];
            s1 += S[nf][2] + S[nf][3];
        }
        s0 += __shfl_xor_sync(0xffffffffu, s0, 1);
        s0 += __shfl_xor_sync(0xffffffffu, s0, 2);
        s1 += __shfl_xor_sync(0xffffffffu, s1, 1);
        s1 += __shfl_xor_sync(0xffffffffu, s1, 2);
        l0 = l0 * a0 + s0; l1 = l1 * a1 + s1;
        m0 = mn0; m1 = mn1;

        #pragma unroll
        for (int nf2 = 0; nf2 < 16; nf2++) {
            O[nf2][0] *= a0; O[nf2][1] *= a0;
            O[nf2][2] *= a1; O[nf2][3] *= a1;
        }

        float* Psm = sm + OFF_PS;
        int prow0 = (w * 16 + g) * PS_STRIDE;
        int prow1 = (w * 16 + g + 8) * PS_STRIDE;
        #pragma unroll
        for (int nf = 0; nf < 8; nf++) {
            *(float2*)(Psm + prow0 + nf * 8 + 2 * tg) = make_float2(rndf(S[nf][0]), rndf(S[nf][1]));
            *(float2*)(Psm + prow1 + nf * 8 + 2 * tg) = make_float2(rndf(S[nf][2]), rndf(S[nf][3]));
        }
        __syncwarp();

        #pragma unroll
        for (int ks2 = 0; ks2 < 8; ks2++) {
            int kc2 = ks2 * 8 + tg;
            uint32_t pa0 = __float_as_uint(Psm[prow0 + kc2]);
            uint32_t pa1 = __float_as_uint(Psm[prow1 + kc2]);
            uint32_t pa2 = __float_as_uint(Psm[prow0 + kc2 + 4]);
            uint32_t pa3 = __float_as_uint(Psm[prow1 + kc2 + 4]);
            #pragma unroll
            for (int nf2 = 0; nf2 < 16; nf2++) {
                uint32_t b0 = __float_as_uint(Vsm[kc2 * VS_STRIDE + nf2 * 8 + g]);
                uint32_t b1 = __float_as_uint(Vsm[(kc2 + 4) * VS_STRIDE + nf2 * 8 + g]);
                mma_tf32(O[nf2][0], O[nf2][1], O[nf2][2], O[nf2][3],
                         pa0, pa1, pa2, pa3, b0, b1);
            }
        }
        __syncthreads();
    }

    float il0 = 1.f / l0, il1 = 1.f / l1;
    size_t base0 = (size_t)(b * T_ + r0) * (H_ * HS_) + h * HS_;
    size_t base1 = base0 + (size_t)8 * (H_ * HS_);
    #pragma unroll
    for (int nf2 = 0; nf2 < 16; nf2++) {
        *(float2*)(Y + base0 + nf2 * 8 + 2 * tg) =
            make_float2(rndf(O[nf2][0] * il0), rndf(O[nf2][1] * il0));
        *(float2*)(Y + base1 + nf2 * 8 + 2 * tg) =
            make_float2(rndf(O[nf2][2] * il1), rndf(O[nf2][3] * il1));
    }
}

// ---------------------------------------------------------------------------
extern "C" void kernel_launch(void* const* d_in, const int* in_sizes, int n_in,
                              void* d_out, int out_size)
{
    const float* q_x  = (const float*)d_in[0];
    const float* kv_x = (const float*)d_in[1];
    const float* Wq   = (const float*)d_in[2];
    const float* bq   = (const float*)d_in[3];
    const float* Wk   = (const float*)d_in[4];
    const float* bk   = (const float*)d_in[5];
    const float* Wv   = (const float*)d_in[6];
    const float* bv   = (const float*)d_in[7];
    const float* Wo   = (const float*)d_in[8];
    const float* bo   = (const float*)d_in[9];
    float* out = (float*)d_out;

    float *qp, *kp, *vp, *yp, *wqT, *wkT, *wvT, *woT, *xq, *xkv;
    cudaGetSymbolAddress((void**)&qp, g_Q);
    cudaGetSymbolAddress((void**)&kp, g_K);
    cudaGetSymbolAddress((void**)&vp, g_V);
    cudaGetSymbolAddress((void**)&yp, g_Y);
    cudaGetSymbolAddress((void**)&wqT, g_WqT);
    cudaGetSymbolAddress((void**)&wkT, g_WkT);
    cudaGetSymbolAddress((void**)&wvT, g_WvT);
    cudaGetSymbolAddress((void**)&woT, g_WoT);
    cudaGetSymbolAddress((void**)&xq, g_Xq);
    cudaGetSymbolAddress((void**)&xkv, g_Xkv);

    const int M = B_ * T_;
    const int NQ = H_ * HS_;

    cudaFuncSetAttribute(mma_gemm_bias, cudaFuncAttributeMaxDynamicSharedMemorySize, GEMM_SMEM);
    cudaFuncSetAttribute(mma_gemm_kv, cudaFuncAttributeMaxDynamicSharedMemorySize, GEMM_SMEM);
    cudaFuncSetAttribute(attn_mma, cudaFuncAttributeMaxDynamicSharedMemorySize, ATTN_SMEM);

    cvt_inputs<<<(unsigned)(2 * N4IN / 256), 256>>>((const float4*)q_x, (const float4*)kv_x,
                                                    (float4*)xq, (float4*)xkv);
    transpose4<<<dim3(128, 128, 4), dim3(32, 8)>>>(Wq, Wk, Wv, Wo, wqT, wkT, wvT, woT);
    mma_gemm_bias<<<dim3(NQ / 128, M / 128), 256, GEMM_SMEM>>>(NQ, xq, wqT, bq, qp);
    mma_gemm_kv<<<dim3(16, M / 128), 256, GEMM_SMEM>>>(xkv, wkT, wvT, bk, bv, kp, vp);
    postproc<<<(unsigned)((PP_Q + PP_K + PP_V4) / 256), 256>>>(qp, kp, vp);
    attn_mma<<<dim3(T_ / 128, H_, B_), 256, ATTN_SMEM>>>(qp, kp, vp, yp);
    mma_gemm_bias<<<dim3(C_ / 128, M / 128), 256, GEMM_SMEM>>>(C_, yp, woT, bo, out);
}

// round 6
// speedup vs baseline: 4.8919x; 1.0710x over previous
#include <cuda_runtime.h>
#include <math.h>
#include <cstdint>

#define B_   2
#define T_   2048
#define C_   4096
#define H_   32
#define KVH_ 8
#define HS_  128
#define GROUPS (H_/KVH_)
#define GK    4096

// ---------------------------------------------------------------------------
// Scratch
// ---------------------------------------------------------------------------
__device__ float g_Q[(size_t)B_*T_*H_*HS_];
__device__ float g_K[(size_t)B_*T_*KVH_*HS_];
__device__ float g_V[(size_t)B_*T_*KVH_*HS_];
__device__ float g_Y[(size_t)B_*T_*H_*HS_];      // k-permuted layout
__device__ float g_WqT[(size_t)C_*H_*HS_];       // [N][K], K k-permuted
__device__ float g_WkT[(size_t)C_*KVH_*HS_];
__device__ float g_WvT[(size_t)C_*KVH_*HS_];
__device__ float g_WoT[(size_t)H_*HS_*C_];
__device__ float g_Xq[(size_t)B_*T_*C_];         // tf32-rounded + k-permuted
__device__ float g_Xkv[(size_t)B_*T_*C_];

// ---------------------------------------------------------------------------
// Helpers
// ---------------------------------------------------------------------------
__device__ __forceinline__ uint32_t smem_to_u32(const void* p) {
    uint32_t a;
    asm("{ .reg .u64 t; cvta.to.shared.u64 t, %1; cvt.u32.u64 %0, t; }" : "=r"(a) : "l"(p));
    return a;
}
__device__ __forceinline__ uint32_t f2tf32(float x) {
    uint32_t u;
    asm("cvt.rna.tf32.f32 %0, %1;" : "=r"(u) : "f"(x));
    return u;
}
__device__ __forceinline__ float rndf(float x) { return __uint_as_float(f2tf32(x)); }

__device__ __forceinline__ void cp_async16(uint32_t smem_addr, const void* gptr) {
    asm volatile("cp.async.cg.shared.global [%0], [%1], 16;" :: "r"(smem_addr), "l"(gptr));
}
#define CP_COMMIT() asm volatile("cp.async.commit_group;" ::: "memory")
#define CP_WAIT(n)  asm volatile("cp.async.wait_group %0;" :: "n"(n) : "memory")

__device__ __forceinline__ void mma_tf32(
    float& d0, float& d1, float& d2, float& d3,
    uint32_t a0, uint32_t a1, uint32_t a2, uint32_t a3,
    uint32_t b0, uint32_t b1)
{
    asm volatile(
        "mma.sync.aligned.m16n8k8.row.col.f32.tf32.tf32.f32 "
        "{%0,%1,%2,%3}, {%4,%5,%6,%7}, {%8,%9}, {%0,%1,%2,%3};"
        : "+f"(d0), "+f"(d1), "+f"(d2), "+f"(d3)
        : "r"(a0), "r"(a1), "r"(a2), "r"(a3), "r"(b0), "r"(b1));
}

// ---------------------------------------------------------------------------
// Launch 1: round inputs to tf32 AND k-pair-permute each aligned 8-block:
// stored[2j] = orig[j], stored[2j+1] = orig[j+4]
// ---------------------------------------------------------------------------
#define N8IN 2097152L   // 4096*4096/8
__global__ void cvt_inputs(const float4* __restrict__ qx, const float4* __restrict__ kvx,
                           float4* __restrict__ oq, float4* __restrict__ okv)
{
    long i = (long)blockIdx.x * blockDim.x + threadIdx.x;
    const float4* s; float4* d; long j;
    if (i < N8IN) { s = qx; d = oq; j = i; }
    else          { s = kvx; d = okv; j = i - N8IN; }
    float4 v0 = s[j * 2], v1 = s[j * 2 + 1];    // orig o0..o3, o4..o7
    float4 w0, w1;
    w0.x = rndf(v0.x); w0.y = rndf(v1.x); w0.z = rndf(v0.y); w0.w = rndf(v1.y);
    w1.x = rndf(v0.z); w1.y = rndf(v1.z); w1.z = rndf(v0.w); w1.w = rndf(v1.w);
    d[j * 2]     = w0;
    d[j * 2 + 1] = w1;
}

// ---------------------------------------------------------------------------
// Launch 2: fused transpose of all 4 weights, tf32-round + k-pair-permute.
// dst[n][k'] where k' = perm(k) within 8-blocks.
// ---------------------------------------------------------------------------
__global__ void transpose4(const float* __restrict__ Wq, const float* __restrict__ Wk,
                           const float* __restrict__ Wv, const float* __restrict__ Wo,
                           float* __restrict__ wqT, float* __restrict__ wkT,
                           float* __restrict__ wvT, float* __restrict__ woT)
{
    __shared__ float tile[32][33];
    int z = blockIdx.z;
    const float* src; float* dst; int rows, cols;
    if (z == 0)      { src = Wq; dst = wqT; rows = 4096; cols = 4096; }
    else if (z == 1) { src = Wk; dst = wkT; rows = 4096; cols = 1024; if (blockIdx.x >= 32) return; }
    else if (z == 2) { src = Wv; dst = wvT; rows = 4096; cols = 1024; if (blockIdx.x >= 32) return; }
    else             { src = Wo; dst = woT; rows = 4096; cols = 4096; }
    int c0 = blockIdx.x * 32, r0 = blockIdx.y * 32;
    int x = threadIdx.x;                         // k index within 32-block
    int jb = x & 7;
    int px = (x & ~7) + ((jb < 4) ? 2 * jb : 2 * (jb - 4) + 1);   // permuted k
    #pragma unroll
    for (int y = threadIdx.y; y < 32; y += 8)
        tile[y][x] = src[(size_t)(r0 + y) * cols + c0 + x];
    __syncthreads();
    #pragma unroll
    for (int y = threadIdx.y; y < 32; y += 8)
        dst[(size_t)(c0 + y) * rows + r0 + px] = rndf(tile[x][y]);
}

// ---------------------------------------------------------------------------
// tf32 mma.sync GEMM core. K-pair-permuted operands -> LDS.64 fragment loads.
// SA=40 (conflict-free for LDS.64), 2 stages (80 KB) -> 2 CTAs/SM.
// ---------------------------------------------------------------------------
#define SA        40
#define STAGES    2
#define STAGE_FLT (2 * 128 * SA)
#define GEMM_SMEM (STAGES * STAGE_FLT * 4)     // 81920
#define KTILES    (GK / 32)

__device__ __forceinline__ void gemm_core(
    int N, const float* __restrict__ A, const float* __restrict__ BT,
    const float* __restrict__ bias, float* __restrict__ C,
    int m0, int n0, float* sm)
{
    uint32_t sb = smem_to_u32(sm);
    int tid  = threadIdx.x;
    int lane = tid & 31, wid = tid >> 5;
    int wr = wid >> 2, wc = wid & 3;
    int g  = lane >> 2, tg = lane & 3;
    int ldRow = tid >> 3;
    int ldC4  = (tid & 7) * 4;

    float acc[4][4][4];
    #pragma unroll
    for (int i = 0; i < 4; i++)
        #pragma unroll
        for (int j = 0; j < 4; j++)
            #pragma unroll
            for (int k = 0; k < 4; k++) acc[i][j][k] = 0.f;

    auto issue_tile = [&](int kt, int s) {
        const float* Ag = A  + (size_t)(m0) * GK + kt * 32;
        const float* Bg = BT + (size_t)(n0) * GK + kt * 32;
        uint32_t stA = sb + (uint32_t)(s * STAGE_FLT) * 4;
        uint32_t stB = stA + (uint32_t)(128 * SA) * 4;
        #pragma unroll
        for (int i = 0; i < 4; i++) {
            int row = ldRow + 32 * i;
            uint32_t soff = (uint32_t)(row * SA + ldC4) * 4;
            cp_async16(stA + soff, Ag + (size_t)row * GK + ldC4);
            cp_async16(stB + soff, Bg + (size_t)row * GK + ldC4);
        }
    };

    issue_tile(0, 0);
    CP_COMMIT();

    for (int kt = 0; kt < KTILES; kt++) {
        int s = kt & 1;
        if (kt + 1 < KTILES) issue_tile(kt + 1, s ^ 1);
        CP_COMMIT();
        CP_WAIT(1);
        __syncthreads();

        const float* As = sm + s * STAGE_FLT;
        const float* Bs = As + 128 * SA;

        #pragma unroll
        for (int ks = 0; ks < 4; ks++) {
            int kb = ks * 8 + 2 * tg;              // permuted pair position
            uint32_t bfr[4][2];
            #pragma unroll
            for (int nt = 0; nt < 4; nt++) {
                float2 lb = *(const float2*)(Bs + (wc * 32 + nt * 8 + g) * SA + kb);
                bfr[nt][0] = __float_as_uint(lb.x);    // orig k = kc
                bfr[nt][1] = __float_as_uint(lb.y);    // orig k = kc+4
            }
            #pragma unroll
            for (int mt = 0; mt < 4; mt++) {
                int ar0 = wr * 64 + mt * 16 + g;
                float2 l0 = *(const float2*)(As + ar0 * SA + kb);
                float2 l1 = *(const float2*)(As + (ar0 + 8) * SA + kb);
                uint32_t a0 = __float_as_uint(l0.x);
                uint32_t a1 = __float_as_uint(l1.x);
                uint32_t a2 = __float_as_uint(l0.y);
                uint32_t a3 = __float_as_uint(l1.y);
                #pragma unroll
                for (int nt = 0; nt < 4; nt++)
                    mma_tf32(acc[mt][nt][0], acc[mt][nt][1], acc[mt][nt][2], acc[mt][nt][3],
                             a0, a1, a2, a3, bfr[nt][0], bfr[nt][1]);
            }
        }
        __syncthreads();
    }

    #pragma unroll
    for (int mt = 0; mt < 4; mt++) {
        int r0 = m0 + wr * 64 + mt * 16 + g;
        #pragma unroll
        for (int nt = 0; nt < 4; nt++) {
            int cc = n0 + wc * 32 + nt * 8 + 2 * tg;
            float2 bv = *(const float2*)(bias + cc);
            float2 o0, o1;
            o0.x = acc[mt][nt][0] + bv.x;
            o0.y = acc[mt][nt][1] + bv.y;
            o1.x = acc[mt][nt][2] + bv.x;
            o1.y = acc[mt][nt][3] + bv.y;
            *(float2*)(C + (size_t)r0 * N + cc)       = o0;
            *(float2*)(C + (size_t)(r0 + 8) * N + cc) = o1;
        }
    }
}

// Launch 3: fused Q+K+V projections (grid.x = 48)
__global__ __launch_bounds__(256, 2) void mma_gemm_qkv(
    const float* __restrict__ Aq, const float* __restrict__ Akv,
    const float* __restrict__ BTq, const float* __restrict__ BTk, const float* __restrict__ BTv,
    const float* __restrict__ bq, const float* __restrict__ bk, const float* __restrict__ bv,
    float* __restrict__ Cq, float* __restrict__ Ck, float* __restrict__ Cv)
{
    extern __shared__ float sm[];
    int bx = blockIdx.x, by = blockIdx.y;
    if (bx < 32)      gemm_core(4096, Aq,  BTq, bq, Cq, by * 128, bx * 128, sm);
    else if (bx < 40) gemm_core(1024, Akv, BTk, bk, Ck, by * 128, (bx - 32) * 128, sm);
    else              gemm_core(1024, Akv, BTv, bv, Cv, by * 128, (bx - 40) * 128, sm);
}

// Launch 6: O projection
__global__ __launch_bounds__(256, 2) void mma_gemm_bias(
    int N, const float* __restrict__ A, const float* __restrict__ BT,
    const float* __restrict__ bias, float* __restrict__ C)
{
    extern __shared__ float sm[];
    gemm_core(N, A, BT, bias, C, blockIdx.y * 128, blockIdx.x * 128, sm);
}

// ---------------------------------------------------------------------------
// Launch 4: fused RoPE(Q) + RoPE(K) + tf32-round(V). (no permutation here:
// these feed attention, which reads them scalar)
// ---------------------------------------------------------------------------
#define PP_Q  8388608L
#define PP_K  2097152L
#define PP_V4 1048576L
__global__ void postproc(float* __restrict__ Q, float* __restrict__ K, float* __restrict__ V)
{
    long i = (long)blockIdx.x * blockDim.x + threadIdx.x;
    if (i < PP_Q + PP_K) {
        float* X; int heads; long idx;
        if (i < PP_Q) { X = Q; heads = H_; idx = i; }
        else          { X = K; heads = KVH_; idx = i - PP_Q; }
        int d = (int)(idx & 63);
        long rh = idx >> 6;
        long row = rh / heads;
        int t = (int)(row % T_);
        float inv = powf(10000.0f, -(float)d * (1.0f / 64.0f));
        float ang = (float)t * inv;
        float c = cosf(ang), s = sinf(ang);
        float* p = X + rh * HS_;
        float x1 = p[d], x2 = p[d + 64];
        p[d]      = rndf(x1 * c - x2 * s);
        p[d + 64] = rndf(x2 * c + x1 * s);
    } else {
        long j = i - (PP_Q + PP_K);
        float4 v = ((float4*)V)[j];
        v.x = rndf(v.x); v.y = rndf(v.y); v.z = rndf(v.z); v.w = rndf(v.w);
        ((float4*)V)[j] = v;
    }
}

// ---------------------------------------------------------------------------
// Launch 5: tensor-core causal flash attention (tf32 mma.sync).
// Y epilogue writes k-permuted layout (feeds O-proj).
// ---------------------------------------------------------------------------
#define KS_STRIDE 132
#define VS_STRIDE 136
#define PS_STRIDE 68
#define OFF_KS0 0
#define OFF_VS0 8448
#define OFF_KS1 17152
#define OFF_VS1 25600
#define OFF_PS  34304
#define ATTN_SMEM (43008 * 4)

__global__ __launch_bounds__(256) void attn_mma(
    const float* __restrict__ Q, const float* __restrict__ K,
    const float* __restrict__ V, float* __restrict__ Y)
{
    extern __shared__ float sm[];
    uint32_t sb = smem_to_u32(sm);
    int tid = threadIdx.x, lane = tid & 31, w = tid >> 5;
    int g = lane >> 2, tg = lane & 3;
    int qb = blockIdx.x, h = blockIdx.y, b = blockIdx.z;
    int kh = h / GROUPS;
    const float scale = 0.08838834764831845f;
    int r0 = qb * 128 + w * 16 + g;

    for (int i = tid; i < 128 * 32; i += 256) {
        int row = i >> 5, c4 = (i & 31) * 4;
        *(float4*)(sm + row * KS_STRIDE + c4) =
            *(const float4*)(Q + (size_t)(b * T_ + qb * 128 + row) * (H_ * HS_) + h * HS_ + c4);
    }
    __syncthreads();
    uint32_t qf[16][4];
    #pragma unroll
    for (int ks = 0; ks < 16; ks++) {
        int kc = ks * 8 + tg;
        qf[ks][0] = f2tf32(sm[(w * 16 + g)     * KS_STRIDE + kc]     * scale);
        qf[ks][1] = f2tf32(sm[(w * 16 + g + 8) * KS_STRIDE + kc]     * scale);
        qf[ks][2] = f2tf32(sm[(w * 16 + g)     * KS_STRIDE + kc + 4] * scale);
        qf[ks][3] = f2tf32(sm[(w * 16 + g + 8) * KS_STRIDE + kc + 4] * scale);
    }
    __syncthreads();

    float O[16][4];
    #pragma unroll
    for (int i = 0; i < 16; i++)
        #pragma unroll
        for (int j = 0; j < 4; j++) O[i][j] = 0.f;
    float m0 = -1e30f, m1 = -1e30f, l0 = 0.f, l1 = 0.f;

    int nt = 2 * qb + 2;

    auto issue_kv = [&](int jt, int s) {
        uint32_t kbase = sb + (uint32_t)(s ? OFF_KS1 : OFF_KS0) * 4;
        uint32_t vbase = sb + (uint32_t)(s ? OFF_VS1 : OFF_VS0) * 4;
        #pragma unroll
        for (int j = 0; j < 8; j++) {
            int ii = tid + 256 * j;
            int row = ii >> 5;
            int c4 = (ii & 31) * 4;
            size_t gidx = ((size_t)(b * T_ + jt * 64 + row) * KVH_ + kh) * HS_ + c4;
            cp_async16(kbase + (uint32_t)(row * KS_STRIDE + c4) * 4, K + gidx);
            cp_async16(vbase + (uint32_t)(row * VS_STRIDE + c4) * 4, V + gidx);
        }
    };

    issue_kv(0, 0);
    CP_COMMIT();

    for (int jt = 0; jt < nt; jt++) {
        if (jt + 1 < nt) issue_kv(jt + 1, (jt + 1) & 1);
        CP_COMMIT();
        CP_WAIT(1);
        __syncthreads();

        const float* Ksm = sm + ((jt & 1) ? OFF_KS1 : OFF_KS0);
        const float* Vsm = sm + ((jt & 1) ? OFF_VS1 : OFF_VS0);

        float S[8][4];
        #pragma unroll
        for (int i = 0; i < 8; i++)
            #pragma unroll
            for (int j = 0; j < 4; j++) S[i][j] = 0.f;

        #pragma unroll
        for (int ks = 0; ks < 16; ks++) {
            int kc = ks * 8 + tg;
            #pragma unroll
            for (int nf = 0; nf < 8; nf++) {
                uint32_t b0 = __float_as_uint(Ksm[(nf * 8 + g) * KS_STRIDE + kc]);
                uint32_t b1 = __float_as_uint(Ksm[(nf * 8 + g) * KS_STRIDE + kc + 4]);
                mma_tf32(S[nf][0], S[nf][1], S[nf][2], S[nf][3],
                         qf[ks][0], qf[ks][1], qf[ks][2], qf[ks][3], b0, b1);
            }
        }

        if (jt >= 2 * qb) {
            int cb = jt * 64;
            #pragma unroll
            for (int nf = 0; nf < 8; nf++) {
                int c0 = cb + nf * 8 + 2 * tg, c1 = c0 + 1;
                if (c0 > r0)     S[nf][0] = -1e30f;
                if (c1 > r0)     S[nf][1] = -1e30f;
                if (c0 > r0 + 8) S[nf][2] = -1e30f;
                if (c1 > r0 + 8) S[nf][3] = -1e30f;
            }
        }

        float mx0 = -1e30f, mx1 = -1e30f;
        #pragma unroll
        for (int nf = 0; nf < 8; nf++) {
            mx0 = fmaxf(mx0, fmaxf(S[nf][0], S[nf][1]));
            mx1 = fmaxf(mx1, fmaxf(S[nf][2], S[nf][3]));
        }
        mx0 = fmaxf(mx0, __shfl_xor_sync(0xffffffffu, mx0, 1));
        mx0 = fmaxf(mx0, __shfl_xor_sync(0xffffffffu, mx0, 2));
        mx1 = fmaxf(mx1, __shfl_xor_sync(0xffffffffu, mx1, 1));
        mx1 = fmaxf(mx1, __shfl_xor_sync(0xffffffffu, mx1, 2));

        float mn0 = fmaxf(m0, mx0), mn1 = fmaxf(m1, mx1);
        float a0 = __expf(m0 - mn0), a1 = __expf(m1 - mn1);
        float s0 = 0.f, s1 = 0.f;
        #pragma unroll
        for (int nf = 0; nf < 8; nf++) {
            S[nf][0] = __expf(S[nf][0] - mn0);
            S[nf][1] = __expf(S[nf][1] - mn0);
            S[nf][2] = __expf(S[nf][2] - mn1);
            S[nf][3] = __expf(S[nf][3] - mn1);
            s0 += S[nf][0] + S[nf][1];
            s1 += S[nf][2] + S[nf][3];
        }
        s0 += __shfl_xor_sync(0xffffffffu, s0, 1);
        s0 += __shfl_xor_sync(0xffffffffu, s0, 2);
        s1 += __shfl_xor_sync(0xffffffffu, s1, 1);
        s1 += __shfl_xor_sync(0xffffffffu, s1, 2);
        l0 = l0 * a0 + s0; l1 = l1 * a1 + s1;
        m0 = mn0; m1 = mn1;

        #pragma unroll
        for (int nf2 = 0; nf2 < 16; nf2++) {
            O[nf2][0] *= a0; O[nf2][1] *= a0;
            O[nf2][2] *= a1; O[nf2][3] *= a1;
        }

        float* Psm = sm + OFF_PS;
        int prow0 = (w * 16 + g) * PS_STRIDE;
        int prow1 = (w * 16 + g + 8) * PS_STRIDE;
        #pragma unroll
        for (int nf = 0; nf < 8; nf++) {
            *(float2*)(Psm + prow0 + nf * 8 + 2 * tg) = make_float2(rndf(S[nf][0]), rndf(S[nf][1]));
            *(float2*)(Psm + prow1 + nf * 8 + 2 * tg) = make_float2(rndf(S[nf][2]), rndf(S[nf][3]));
        }
        __syncwarp();

        #pragma unroll
        for (int ks2 = 0; ks2 < 8; ks2++) {
            int kc2 = ks2 * 8 + tg;
            uint32_t pa0 = __float_as_uint(Psm[prow0 + kc2]);
            uint32_t pa1 = __float_as_uint(Psm[prow1 + kc2]);
            uint32_t pa2 = __float_as_uint(Psm[prow0 + kc2 + 4]);
            uint32_t pa3 = __float_as_uint(Psm[prow1 + kc2 + 4]);
            #pragma unroll
            for (int nf2 = 0; nf2 < 16; nf2++) {
                uint32_t b0 = __float_as_uint(Vsm[kc2 * VS_STRIDE + nf2 * 8 + g]);
                uint32_t b1 = __float_as_uint(Vsm[(kc2 + 4) * VS_STRIDE + nf2 * 8 + g]);
                mma_tf32(O[nf2][0], O[nf2][1], O[nf2][2], O[nf2][3],
                         pa0, pa1, pa2, pa3, b0, b1);
            }
        }
        __syncthreads();
    }

    // ---- epilogue: normalize, tf32-round, store k-PERMUTED for O-proj ----
    float il0 = 1.f / l0, il1 = 1.f / l1;
    size_t base0 = (size_t)(b * T_ + r0) * (H_ * HS_) + h * HS_;
    size_t base1 = base0 + (size_t)8 * (H_ * HS_);
    int pc = (tg < 2) ? 4 * tg : 4 * tg - 7;     // sigma(2tg); sigma(2tg+1)=pc+2
    #pragma unroll
    for (int nf2 = 0; nf2 < 16; nf2++) {
        Y[base0 + nf2 * 8 + pc]     = rndf(O[nf2][0] * il0);
        Y[base0 + nf2 * 8 + pc + 2] = rndf(O[nf2][1] * il0);
        Y[base1 + nf2 * 8 + pc]     = rndf(O[nf2][2] * il1);
        Y[base1 + nf2 * 8 + pc + 2] = rndf(O[nf2][3] * il1);
    }
}

// ---------------------------------------------------------------------------
extern "C" void kernel_launch(void* const* d_in, const int* in_sizes, int n_in,
                              void* d_out, int out_size)
{
    const float* q_x  = (const float*)d_in[0];
    const float* kv_x = (const float*)d_in[1];
    const float* Wq   = (const float*)d_in[2];
    const float* bq   = (const float*)d_in[3];
    const float* Wk   = (const float*)d_in[4];
    const float* bk   = (const float*)d_in[5];
    const float* Wv   = (const float*)d_in[6];
    const float* bv   = (const float*)d_in[7];
    const float* Wo   = (const float*)d_in[8];
    const float* bo   = (const float*)d_in[9];
    float* out = (float*)d_out;

    float *qp, *kp, *vp, *yp, *wqT, *wkT, *wvT, *woT, *xq, *xkv;
    cudaGetSymbolAddress((void**)&qp, g_Q);
    cudaGetSymbolAddress((void**)&kp, g_K);
    cudaGetSymbolAddress((void**)&vp, g_V);
    cudaGetSymbolAddress((void**)&yp, g_Y);
    cudaGetSymbolAddress((void**)&wqT, g_WqT);
    cudaGetSymbolAddress((void**)&wkT, g_WkT);
    cudaGetSymbolAddress((void**)&wvT, g_WvT);
    cudaGetSymbolAddress((void**)&woT, g_WoT);
    cudaGetSymbolAddress((void**)&xq, g_Xq);
    cudaGetSymbolAddress((void**)&xkv, g_Xkv);

    const int M = B_ * T_;

    cudaFuncSetAttribute(mma_gemm_qkv, cudaFuncAttributeMaxDynamicSharedMemorySize, GEMM_SMEM);
    cudaFuncSetAttribute(mma_gemm_bias, cudaFuncAttributeMaxDynamicSharedMemorySize, GEMM_SMEM);
    cudaFuncSetAttribute(attn_mma, cudaFuncAttributeMaxDynamicSharedMemorySize, ATTN_SMEM);

    // 1. round + permute inputs
    cvt_inputs<<<(unsigned)(2 * N8IN / 256), 256>>>((const float4*)q_x, (const float4*)kv_x,
                                                    (float4*)xq, (float4*)xkv);
    // 2. transpose + round + permute weights
    transpose4<<<dim3(128, 128, 4), dim3(32, 8)>>>(Wq, Wk, Wv, Wo, wqT, wkT, wvT, woT);
    // 3. fused Q+K+V projections
    mma_gemm_qkv<<<dim3(48, M / 128), 256, GEMM_SMEM>>>(xq, xkv, wqT, wkT, wvT,
                                                        bq, bk, bv, qp, kp, vp);
    // 4. RoPE(Q,K) + round(V)
    postproc<<<(unsigned)((PP_Q + PP_K + PP_V4) / 256), 256>>>(qp, kp, vp);
    // 5. attention
    attn_mma<<<dim3(T_ / 128, H_, B_), 256, ATTN_SMEM>>>(qp, kp, vp, yp);
    // 6. output projection
    mma_gemm_bias<<<dim3(C_ / 128, M / 128), 256, GEMM_SMEM>>>(C_, yp, woT, bo, out);
}

// round 7
// speedup vs baseline: 4.9855x; 1.0191x over previous
#include <cuda_runtime.h>
#include <math.h>
#include <cstdint>

#define B_   2
#define T_   2048
#define C_   4096
#define H_   32
#define KVH_ 8
#define HS_  128
#define GROUPS (H_/KVH_)
#define GK    4096

// ---------------------------------------------------------------------------
// Scratch
// ---------------------------------------------------------------------------
__device__ float g_Q[(size_t)B_*T_*H_*HS_];
__device__ float g_K[(size_t)B_*T_*KVH_*HS_];
__device__ float g_V[(size_t)B_*T_*KVH_*HS_];
__device__ float g_Y[(size_t)B_*T_*H_*HS_];      // k-permuted layout
__device__ float g_WqT[(size_t)C_*H_*HS_];       // [N][K], K k-permuted
__device__ float g_WkT[(size_t)C_*KVH_*HS_];
__device__ float g_WvT[(size_t)C_*KVH_*HS_];
__device__ float g_WoT[(size_t)H_*HS_*C_];
__device__ float g_Xq[(size_t)B_*T_*C_];         // tf32-rounded + k-permuted
__device__ float g_Xkv[(size_t)B_*T_*C_];

// ---------------------------------------------------------------------------
// Helpers
// ---------------------------------------------------------------------------
__device__ __forceinline__ uint32_t smem_to_u32(const void* p) {
    uint32_t a;
    asm("{ .reg .u64 t; cvta.to.shared.u64 t, %1; cvt.u32.u64 %0, t; }" : "=r"(a) : "l"(p));
    return a;
}
__device__ __forceinline__ uint32_t f2tf32(float x) {
    uint32_t u;
    asm("cvt.rna.tf32.f32 %0, %1;" : "=r"(u) : "f"(x));
    return u;
}
__device__ __forceinline__ float rndf(float x) { return __uint_as_float(f2tf32(x)); }

__device__ __forceinline__ void cp_async16(uint32_t smem_addr, const void* gptr) {
    asm volatile("cp.async.cg.shared.global [%0], [%1], 16;" :: "r"(smem_addr), "l"(gptr));
}
#define CP_COMMIT() asm volatile("cp.async.commit_group;" ::: "memory")
#define CP_WAIT(n)  asm volatile("cp.async.wait_group %0;" :: "n"(n) : "memory")

__device__ __forceinline__ void mma_tf32(
    float& d0, float& d1, float& d2, float& d3,
    uint32_t a0, uint32_t a1, uint32_t a2, uint32_t a3,
    uint32_t b0, uint32_t b1)
{
    asm volatile(
        "mma.sync.aligned.m16n8k8.row.col.f32.tf32.tf32.f32 "
        "{%0,%1,%2,%3}, {%4,%5,%6,%7}, {%8,%9}, {%0,%1,%2,%3};"
        : "+f"(d0), "+f"(d1), "+f"(d2), "+f"(d3)
        : "r"(a0), "r"(a1), "r"(a2), "r"(a3), "r"(b0), "r"(b1));
}

// ---------------------------------------------------------------------------
// Launch 1: merged prep.
// z<4: transpose weight z, tf32-round + k-pair-permute K dim.
// z=4: round + k-pair-permute both inputs.
// ---------------------------------------------------------------------------
#define N8IN 2097152L   // 4096*4096/8
__global__ void prep_kernel(
    const float* __restrict__ Wq, const float* __restrict__ Wk,
    const float* __restrict__ Wv, const float* __restrict__ Wo,
    float* __restrict__ wqT, float* __restrict__ wkT,
    float* __restrict__ wvT, float* __restrict__ woT,
    const float4* __restrict__ qx, const float4* __restrict__ kvx,
    float4* __restrict__ oq, float4* __restrict__ okv)
{
    int z = blockIdx.z;
    int tid = threadIdx.x;
    if (z == 4) {
        // input rounding + permutation: 16384 blocks x 256 threads, 2 tensors
        long i = ((long)(blockIdx.y * 128 + blockIdx.x)) * 256 + tid;
        const float4* s; float4* d; long j;
        if (i < N8IN) { s = qx; d = oq; j = i; }
        else          { s = kvx; d = okv; j = i - N8IN; }
        float4 v0 = s[j * 2], v1 = s[j * 2 + 1];
        float4 w0, w1;
        w0.x = rndf(v0.x); w0.y = rndf(v1.x); w0.z = rndf(v0.y); w0.w = rndf(v1.y);
        w1.x = rndf(v0.z); w1.y = rndf(v1.z); w1.z = rndf(v0.w); w1.w = rndf(v1.w);
        d[j * 2]     = w0;
        d[j * 2 + 1] = w1;
        return;
    }
    __shared__ float tile[32][33];
    const float* src; float* dst; int rows, cols;
    if (z == 0)      { src = Wq; dst = wqT; rows = 4096; cols = 4096; }
    else if (z == 1) { src = Wk; dst = wkT; rows = 4096; cols = 1024; if (blockIdx.x >= 32) return; }
    else if (z == 2) { src = Wv; dst = wvT; rows = 4096; cols = 1024; if (blockIdx.x >= 32) return; }
    else             { src = Wo; dst = woT; rows = 4096; cols = 4096; }
    int c0 = blockIdx.x * 32, r0 = blockIdx.y * 32;
    int x = tid & 31, y0 = tid >> 5;
    int jb = x & 7;
    int px = (x & ~7) + ((jb < 4) ? 2 * jb : 2 * (jb - 4) + 1);
    #pragma unroll
    for (int y = y0; y < 32; y += 8)
        tile[y][x] = src[(size_t)(r0 + y) * cols + c0 + x];
    __syncthreads();
    #pragma unroll
    for (int y = y0; y < 32; y += 8)
        dst[(size_t)(c0 + y) * rows + r0 + px] = rndf(tile[x][y]);
}

// ---------------------------------------------------------------------------
// tf32 mma.sync GEMM core. K-pair-permuted operands -> LDS.64 fragment loads.
// SA=40 conflict-free, 2 stages, 2 CTAs/SM, ONE sync per k-tile.
// ---------------------------------------------------------------------------
#define SA        40
#define STAGES    2
#define STAGE_FLT (2 * 128 * SA)
#define GEMM_SMEM (STAGES * STAGE_FLT * 4)     // 81920
#define KTILES    (GK / 32)

__device__ __forceinline__ void gemm_core(
    int N, const float* __restrict__ A, const float* __restrict__ BT,
    const float* __restrict__ bias, float* __restrict__ C,
    int m0, int n0, float* sm)
{
    uint32_t sb = smem_to_u32(sm);
    int tid  = threadIdx.x;
    int lane = tid & 31, wid = tid >> 5;
    int wr = wid >> 2, wc = wid & 3;
    int g  = lane >> 2, tg = lane & 3;
    int ldRow = tid >> 3;
    int ldC4  = (tid & 7) * 4;

    float acc[4][4][4];
    #pragma unroll
    for (int i = 0; i < 4; i++)
        #pragma unroll
        for (int j = 0; j < 4; j++)
            #pragma unroll
            for (int k = 0; k < 4; k++) acc[i][j][k] = 0.f;

    auto issue_tile = [&](int kt, int s) {
        const float* Ag = A  + (size_t)(m0) * GK + kt * 32;
        const float* Bg = BT + (size_t)(n0) * GK + kt * 32;
        uint32_t stA = sb + (uint32_t)(s * STAGE_FLT) * 4;
        uint32_t stB = stA + (uint32_t)(128 * SA) * 4;
        #pragma unroll
        for (int i = 0; i < 4; i++) {
            int row = ldRow + 32 * i;
            uint32_t soff = (uint32_t)(row * SA + ldC4) * 4;
            cp_async16(stA + soff, Ag + (size_t)row * GK + ldC4);
            cp_async16(stB + soff, Bg + (size_t)row * GK + ldC4);
        }
    };

    issue_tile(0, 0);
    CP_COMMIT();

    for (int kt = 0; kt < KTILES; kt++) {
        int s = kt & 1;
        CP_WAIT(0);            // tile kt complete (only group in flight)
        __syncthreads();       // publishes kt; proves kt-1 reads done -> buf^1 free
        if (kt + 1 < KTILES) { issue_tile(kt + 1, s ^ 1); CP_COMMIT(); }

        const float* As = sm + s * STAGE_FLT;
        const float* Bs = As + 128 * SA;

        #pragma unroll
        for (int ks = 0; ks < 4; ks++) {
            int kb = ks * 8 + 2 * tg;
            uint32_t bfr[4][2];
            #pragma unroll
            for (int nt = 0; nt < 4; nt++) {
                float2 lb = *(const float2*)(Bs + (wc * 32 + nt * 8 + g) * SA + kb);
                bfr[nt][0] = __float_as_uint(lb.x);
                bfr[nt][1] = __float_as_uint(lb.y);
            }
            #pragma unroll
            for (int mt = 0; mt < 4; mt++) {
                int ar0 = wr * 64 + mt * 16 + g;
                float2 l0 = *(const float2*)(As + ar0 * SA + kb);
                float2 l1 = *(const float2*)(As + (ar0 + 8) * SA + kb);
                uint32_t a0 = __float_as_uint(l0.x);
                uint32_t a1 = __float_as_uint(l1.x);
                uint32_t a2 = __float_as_uint(l0.y);
                uint32_t a3 = __float_as_uint(l1.y);
                #pragma unroll
                for (int nt = 0; nt < 4; nt++)
                    mma_tf32(acc[mt][nt][0], acc[mt][nt][1], acc[mt][nt][2], acc[mt][nt][3],
                             a0, a1, a2, a3, bfr[nt][0], bfr[nt][1]);
            }
        }
    }

    #pragma unroll
    for (int mt = 0; mt < 4; mt++) {
        int r0 = m0 + wr * 64 + mt * 16 + g;
        #pragma unroll
        for (int nt = 0; nt < 4; nt++) {
            int cc = n0 + wc * 32 + nt * 8 + 2 * tg;
            float2 bv = *(const float2*)(bias + cc);
            float2 o0, o1;
            o0.x = acc[mt][nt][0] + bv.x;
            o0.y = acc[mt][nt][1] + bv.y;
            o1.x = acc[mt][nt][2] + bv.x;
            o1.y = acc[mt][nt][3] + bv.y;
            *(float2*)(C + (size_t)r0 * N + cc)       = o0;
            *(float2*)(C + (size_t)(r0 + 8) * N + cc) = o1;
        }
    }
}

// Launch 2: fused Q+K+V projections (grid.x = 48)
__global__ __launch_bounds__(256, 2) void mma_gemm_qkv(
    const float* __restrict__ Aq, const float* __restrict__ Akv,
    const float* __restrict__ BTq, const float* __restrict__ BTk, const float* __restrict__ BTv,
    const float* __restrict__ bq, const float* __restrict__ bk, const float* __restrict__ bv,
    float* __restrict__ Cq, float* __restrict__ Ck, float* __restrict__ Cv)
{
    extern __shared__ float sm[];
    int bx = blockIdx.x, by = blockIdx.y;
    if (bx < 32)      gemm_core(4096, Aq,  BTq, bq, Cq, by * 128, bx * 128, sm);
    else if (bx < 40) gemm_core(1024, Akv, BTk, bk, Ck, by * 128, (bx - 32) * 128, sm);
    else              gemm_core(1024, Akv, BTv, bv, Cv, by * 128, (bx - 40) * 128, sm);
}

// Launch 5: O projection
__global__ __launch_bounds__(256, 2) void mma_gemm_bias(
    int N, const float* __restrict__ A, const float* __restrict__ BT,
    const float* __restrict__ bias, float* __restrict__ C)
{
    extern __shared__ float sm[];
    gemm_core(N, A, BT, bias, C, blockIdx.y * 128, blockIdx.x * 128, sm);
}

// ---------------------------------------------------------------------------
// Launch 3: fused RoPE(Q) + RoPE(K) + tf32-round(V).
// ---------------------------------------------------------------------------
#define PP_Q  8388608L
#define PP_K  2097152L
#define PP_V4 1048576L
#define LOG2_10000_D64 0.20762050593048358f
__global__ void postproc(float* __restrict__ Q, float* __restrict__ K, float* __restrict__ V)
{
    long i = (long)blockIdx.x * blockDim.x + threadIdx.x;
    if (i < PP_Q + PP_K) {
        float* X; int heads; long idx;
        if (i < PP_Q) { X = Q; heads = H_; idx = i; }
        else          { X = K; heads = KVH_; idx = i - PP_Q; }
        int d = (int)(idx & 63);
        long rh = idx >> 6;
        long row = rh / heads;
        int t = (int)(row % T_);
        float inv = exp2f(-(float)d * LOG2_10000_D64);
        float ang = (float)t * inv;
        float c = cosf(ang), s = sinf(ang);
        float* p = X + rh * HS_;
        float x1 = p[d], x2 = p[d + 64];
        p[d]      = rndf(x1 * c - x2 * s);
        p[d + 64] = rndf(x2 * c + x1 * s);
    } else {
        long j = i - (PP_Q + PP_K);
        float4 v = ((float4*)V)[j];
        v.x = rndf(v.x); v.y = rndf(v.y); v.z = rndf(v.z); v.w = rndf(v.w);
        ((float4*)V)[j] = v;
    }
}

// ---------------------------------------------------------------------------
// Launch 4: tensor-core causal flash attention. Reversed qb scheduling.
// ---------------------------------------------------------------------------
#define KS_STRIDE 132
#define VS_STRIDE 136
#define PS_STRIDE 68
#define OFF_KS0 0
#define OFF_VS0 8448
#define OFF_KS1 17152
#define OFF_VS1 25600
#define OFF_PS  34304
#define ATTN_SMEM (43008 * 4)

__global__ __launch_bounds__(256) void attn_mma(
    const float* __restrict__ Q, const float* __restrict__ K,
    const float* __restrict__ V, float* __restrict__ Y)
{
    extern __shared__ float sm[];
    uint32_t sb = smem_to_u32(sm);
    int tid = threadIdx.x, lane = tid & 31, w = tid >> 5;
    int g = lane >> 2, tg = lane & 3;
    int qb = gridDim.x - 1 - blockIdx.x;         // heavy blocks launch first
    int h = blockIdx.y, b = blockIdx.z;
    int kh = h / GROUPS;
    const float scale = 0.08838834764831845f;
    int r0 = qb * 128 + w * 16 + g;

    for (int i = tid; i < 128 * 32; i += 256) {
        int row = i >> 5, c4 = (i & 31) * 4;
        *(float4*)(sm + row * KS_STRIDE + c4) =
            *(const float4*)(Q + (size_t)(b * T_ + qb * 128 + row) * (H_ * HS_) + h * HS_ + c4);
    }
    __syncthreads();
    uint32_t qf[16][4];
    #pragma unroll
    for (int ks = 0; ks < 16; ks++) {
        int kc = ks * 8 + tg;
        qf[ks][0] = f2tf32(sm[(w * 16 + g)     * KS_STRIDE + kc]     * scale);
        qf[ks][1] = f2tf32(sm[(w * 16 + g + 8) * KS_STRIDE + kc]     * scale);
        qf[ks][2] = f2tf32(sm[(w * 16 + g)     * KS_STRIDE + kc + 4] * scale);
        qf[ks][3] = f2tf32(sm[(w * 16 + g + 8) * KS_STRIDE + kc + 4] * scale);
    }
    __syncthreads();

    float O[16][4];
    #pragma unroll
    for (int i = 0; i < 16; i++)
        #pragma unroll
        for (int j = 0; j < 4; j++) O[i][j] = 0.f;
    float m0 = -1e30f, m1 = -1e30f, l0 = 0.f, l1 = 0.f;

    int nt = 2 * qb + 2;

    auto issue_kv = [&](int jt, int s) {
        uint32_t kbase = sb + (uint32_t)(s ? OFF_KS1 : OFF_KS0) * 4;
        uint32_t vbase = sb + (uint32_t)(s ? OFF_VS1 : OFF_VS0) * 4;
        #pragma unroll
        for (int j = 0; j < 8; j++) {
            int ii = tid + 256 * j;
            int row = ii >> 5;
            int c4 = (ii & 31) * 4;
            size_t gidx = ((size_t)(b * T_ + jt * 64 + row) * KVH_ + kh) * HS_ + c4;
            cp_async16(kbase + (uint32_t)(row * KS_STRIDE + c4) * 4, K + gidx);
            cp_async16(vbase + (uint32_t)(row * VS_STRIDE + c4) * 4, V + gidx);
        }
    };

    issue_kv(0, 0);
    CP_COMMIT();

    for (int jt = 0; jt < nt; jt++) {
        if (jt + 1 < nt) issue_kv(jt + 1, (jt + 1) & 1);
        CP_COMMIT();
        CP_WAIT(1);
        __syncthreads();

        const float* Ksm = sm + ((jt & 1) ? OFF_KS1 : OFF_KS0);
        const float* Vsm = sm + ((jt & 1) ? OFF_VS1 : OFF_VS0);

        float S[8][4];
        #pragma unroll
        for (int i = 0; i < 8; i++)
            #pragma unroll
            for (int j = 0; j < 4; j++) S[i][j] = 0.f;

        #pragma unroll
        for (int ks = 0; ks < 16; ks++) {
            int kc = ks * 8 + tg;
            #pragma unroll
            for (int nf = 0; nf < 8; nf++) {
                uint32_t b0 = __float_as_uint(Ksm[(nf * 8 + g) * KS_STRIDE + kc]);
                uint32_t b1 = __float_as_uint(Ksm[(nf * 8 + g) * KS_STRIDE + kc + 4]);
                mma_tf32(S[nf][0], S[nf][1], S[nf][2], S[nf][3],
                         qf[ks][0], qf[ks][1], qf[ks][2], qf[ks][3], b0, b1);
            }
        }

        if (jt >= 2 * qb) {
            int cb = jt * 64;
            #pragma unroll
            for (int nf = 0; nf < 8; nf++) {
                int c0 = cb + nf * 8 + 2 * tg, c1 = c0 + 1;
                if (c0 > r0)     S[nf][0] = -1e30f;
                if (c1 > r0)     S[nf][1] = -1e30f;
                if (c0 > r0 + 8) S[nf][2] = -1e30f;
                if (c1 > r0 + 8) S[nf][3] = -1e30f;
            }
        }

        float mx0 = -1e30f, mx1 = -1e30f;
        #pragma unroll
        for (int nf = 0; nf < 8; nf++) {
            mx0 = fmaxf(mx0, fmaxf(S[nf][0], S[nf][1]));
            mx1 = fmaxf(mx1, fmaxf(S[nf][2], S[nf][3]));
        }
        mx0 = fmaxf(mx0, __shfl_xor_sync(0xffffffffu, mx0, 1));
        mx0 = fmaxf(mx0, __shfl_xor_sync(0xffffffffu, mx0, 2));
        mx1 = fmaxf(mx1, __shfl_xor_sync(0xffffffffu, mx1, 1));
        mx1 = fmaxf(mx1, __shfl_xor_sync(0xffffffffu, mx1, 2));

        float mn0 = fmaxf(m0, mx0), mn1 = fmaxf(m1, mx1);
        float a0 = __expf(m0 - mn0), a1 = __expf(m1 - mn1);
        float s0 = 0.f, s1 = 0.f;
        #pragma unroll
        for (int nf = 0; nf < 8; nf++) {
            S[nf][0] = __expf(S[nf][0] - mn0);
            S[nf][1] = __expf(S[nf][1] - mn0);
            S[nf][2] = __expf(S[nf][2] - mn1);
            S[nf][3] = __expf(S[nf][3] - mn1);
            s0 += S[nf][0] + S[nf][1];
            s1 += S[nf][2] + S[nf][3];
        }
        s0 += __shfl_xor_sync(0xffffffffu, s0, 1);
        s0 += __shfl_xor_sync(0xffffffffu, s0, 2);
        s1 += __shfl_xor_sync(0xffffffffu, s1, 1);
        s1 += __shfl_xor_sync(0xffffffffu, s1, 2);
        l0 = l0 * a0 + s0; l1 = l1 * a1 + s1;
        m0 = mn0; m1 = mn1;

        #pragma unroll
        for (int nf2 = 0; nf2 < 16; nf2++) {
            O[nf2][0] *= a0; O[nf2][1] *= a0;
            O[nf2][2] *= a1; O[nf2][3] *= a1;
        }

        float* Psm = sm + OFF_PS;
        int prow0 = (w * 16 + g) * PS_STRIDE;
        int prow1 = (w * 16 + g + 8) * PS_STRIDE;
        #pragma unroll
        for (int nf = 0; nf < 8; nf++) {
            *(float2*)(Psm + prow0 + nf * 8 + 2 * tg) = make_float2(rndf(S[nf][0]), rndf(S[nf][1]));
            *(float2*)(Psm + prow1 + nf * 8 + 2 * tg) = make_float2(rndf(S[nf][2]), rndf(S[nf][3]));
        }
        __syncwarp();

        #pragma unroll
        for (int ks2 = 0; ks2 < 8; ks2++) {
            int kc2 = ks2 * 8 + tg;
            uint32_t pa0 = __float_as_uint(Psm[prow0 + kc2]);
            uint32_t pa1 = __float_as_uint(Psm[prow1 + kc2]);
            uint32_t pa2 = __float_as_uint(Psm[prow0 + kc2 + 4]);
            uint32_t pa3 = __float_as_uint(Psm[prow1 + kc2 + 4]);
            #pragma unroll
            for (int nf2 = 0; nf2 < 16; nf2++) {
                uint32_t b0 = __float_as_uint(Vsm[kc2 * VS_STRIDE + nf2 * 8 + g]);
                uint32_t b1 = __float_as_uint(Vsm[(kc2 + 4) * VS_STRIDE + nf2 * 8 + g]);
                mma_tf32(O[nf2][0], O[nf2][1], O[nf2][2], O[nf2][3],
                         pa0, pa1, pa2, pa3, b0, b1);
            }
        }
        __syncthreads();
    }

    float il0 = 1.f / l0, il1 = 1.f / l1;
    size_t base0 = (size_t)(b * T_ + r0) * (H_ * HS_) + h * HS_;
    size_t base1 = base0 + (size_t)8 * (H_ * HS_);
    int pc = (tg < 2) ? 4 * tg : 4 * tg - 7;
    #pragma unroll
    for (int nf2 = 0; nf2 < 16; nf2++) {
        Y[base0 + nf2 * 8 + pc]     = rndf(O[nf2][0] * il0);
        Y[base0 + nf2 * 8 + pc + 2] = rndf(O[nf2][1] * il0);
        Y[base1 + nf2 * 8 + pc]     = rndf(O[nf2][2] * il1);
        Y[base1 + nf2 * 8 + pc + 2] = rndf(O[nf2][3] * il1);
    }
}

// ---------------------------------------------------------------------------
extern "C" void kernel_launch(void* const* d_in, const int* in_sizes, int n_in,
                              void* d_out, int out_size)
{
    const float* q_x  = (const float*)d_in[0];
    const float* kv_x = (const float*)d_in[1];
    const float* Wq   = (const float*)d_in[2];
    const float* bq   = (const float*)d_in[3];
    const float* Wk   = (const float*)d_in[4];
    const float* bk   = (const float*)d_in[5];
    const float* Wv   = (const float*)d_in[6];
    const float* bv   = (const float*)d_in[7];
    const float* Wo   = (const float*)d_in[8];
    const float* bo   = (const float*)d_in[9];
    float* out = (float*)d_out;

    float *qp, *kp, *vp, *yp, *wqT, *wkT, *wvT, *woT, *xq, *xkv;
    cudaGetSymbolAddress((void**)&qp, g_Q);
    cudaGetSymbolAddress((void**)&kp, g_K);
    cudaGetSymbolAddress((void**)&vp, g_V);
    cudaGetSymbolAddress((void**)&yp, g_Y);
    cudaGetSymbolAddress((void**)&wqT, g_WqT);
    cudaGetSymbolAddress((void**)&wkT, g_WkT);
    cudaGetSymbolAddress((void**)&wvT, g_WvT);
    cudaGetSymbolAddress((void**)&woT, g_WoT);
    cudaGetSymbolAddress((void**)&xq, g_Xq);
    cudaGetSymbolAddress((void**)&xkv, g_Xkv);

    const int M = B_ * T_;

    cudaFuncSetAttribute(mma_gemm_qkv, cudaFuncAttributeMaxDynamicSharedMemorySize, GEMM_SMEM);
    cudaFuncSetAttribute(mma_gemm_bias, cudaFuncAttributeMaxDynamicSharedMemorySize, GEMM_SMEM);
    cudaFuncSetAttribute(attn_mma, cudaFuncAttributeMaxDynamicSharedMemorySize, ATTN_SMEM);

    // 1. merged prep: weight transposes + input rounding/permutation
    prep_kernel<<<dim3(128, 128, 5), 256>>>(Wq, Wk, Wv, Wo, wqT, wkT, wvT, woT,
                                            (const float4*)q_x, (const float4*)kv_x,
                                            (float4*)xq, (float4*)xkv);
    // 2. fused Q+K+V projections
    mma_gemm_qkv<<<dim3(48, M / 128), 256, GEMM_SMEM>>>(xq, xkv, wqT, wkT, wvT,
                                                        bq, bk, bv, qp, kp, vp);
    // 3. RoPE(Q,K) + round(V)
    postproc<<<(unsigned)((PP_Q + PP_K + PP_V4) / 256), 256>>>(qp, kp, vp);
    // 4. attention (profiled slot)
    attn_mma<<<dim3(T_ / 128, H_, B_), 256, ATTN_SMEM>>>(qp, kp, vp, yp);
    // 5. output projection
    mma_gemm_bias<<<dim3(C_ / 128, M / 128), 256, GEMM_SMEM>>>(C_, yp, woT, bo, out);
}

// round 8
// speedup vs baseline: 5.0645x; 1.0159x over previous
#include <cuda_runtime.h>
#include <math.h>
#include <cstdint>

#define B_   2
#define T_   2048
#define C_   4096
#define H_   32
#define KVH_ 8
#define HS_  128
#define GROUPS (H_/KVH_)
#define GK    4096

// ---------------------------------------------------------------------------
// Scratch
// ---------------------------------------------------------------------------
__device__ float g_Q[(size_t)B_*T_*H_*HS_];      // d-permuted after postproc
__device__ float g_K[(size_t)B_*T_*KVH_*HS_];    // d-permuted after postproc
__device__ float g_V[(size_t)B_*T_*KVH_*HS_];    // raw from gemm
__device__ float g_Vt[(size_t)B_*KVH_*HS_*T_];   // V^T, t-permuted, tf32
__device__ float g_Y[(size_t)B_*T_*H_*HS_];      // k-permuted layout
__device__ float g_WqT[(size_t)C_*H_*HS_];       // [N][K], K k-permuted
__device__ float g_WkT[(size_t)C_*KVH_*HS_];
__device__ float g_WvT[(size_t)C_*KVH_*HS_];
__device__ float g_WoT[(size_t)H_*HS_*C_];
__device__ float g_Xq[(size_t)B_*T_*C_];         // tf32-rounded + k-permuted
__device__ float g_Xkv[(size_t)B_*T_*C_];

// ---------------------------------------------------------------------------
// Helpers
// ---------------------------------------------------------------------------
__device__ __forceinline__ uint32_t smem_to_u32(const void* p) {
    uint32_t a;
    asm("{ .reg .u64 t; cvta.to.shared.u64 t, %1; cvt.u32.u64 %0, t; }" : "=r"(a) : "l"(p));
    return a;
}
__device__ __forceinline__ uint32_t f2tf32(float x) {
    uint32_t u;
    asm("cvt.rna.tf32.f32 %0, %1;" : "=r"(u) : "f"(x));
    return u;
}
__device__ __forceinline__ float rndf(float x) { return __uint_as_float(f2tf32(x)); }

__device__ __forceinline__ void cp_async16(uint32_t smem_addr, const void* gptr) {
    asm volatile("cp.async.cg.shared.global [%0], [%1], 16;" :: "r"(smem_addr), "l"(gptr));
}
#define CP_COMMIT() asm volatile("cp.async.commit_group;" ::: "memory")
#define CP_WAIT(n)  asm volatile("cp.async.wait_group %0;" :: "n"(n) : "memory")

__device__ __forceinline__ void mma_tf32(
    float& d0, float& d1, float& d2, float& d3,
    uint32_t a0, uint32_t a1, uint32_t a2, uint32_t a3,
    uint32_t b0, uint32_t b1)
{
    asm volatile(
        "mma.sync.aligned.m16n8k8.row.col.f32.tf32.tf32.f32 "
        "{%0,%1,%2,%3}, {%4,%5,%6,%7}, {%8,%9}, {%0,%1,%2,%3};"
        : "+f"(d0), "+f"(d1), "+f"(d2), "+f"(d3)
        : "r"(a0), "r"(a1), "r"(a2), "r"(a3), "r"(b0), "r"(b1));
}

// ---------------------------------------------------------------------------
// Launch 1: merged prep (weight transposes + input round/permute)
// ---------------------------------------------------------------------------
#define N8IN 2097152L   // 4096*4096/8
__global__ void prep_kernel(
    const float* __restrict__ Wq, const float* __restrict__ Wk,
    const float* __restrict__ Wv, const float* __restrict__ Wo,
    float* __restrict__ wqT, float* __restrict__ wkT,
    float* __restrict__ wvT, float* __restrict__ woT,
    const float4* __restrict__ qx, const float4* __restrict__ kvx,
    float4* __restrict__ oq, float4* __restrict__ okv)
{
    int z = blockIdx.z;
    int tid = threadIdx.x;
    if (z == 4) {
        long i = ((long)(blockIdx.y * 128 + blockIdx.x)) * 256 + tid;
        const float4* s; float4* d; long j;
        if (i < N8IN) { s = qx; d = oq; j = i; }
        else          { s = kvx; d = okv; j = i - N8IN; }
        float4 v0 = s[j * 2], v1 = s[j * 2 + 1];
        float4 w0, w1;
        w0.x = rndf(v0.x); w0.y = rndf(v1.x); w0.z = rndf(v0.y); w0.w = rndf(v1.y);
        w1.x = rndf(v0.z); w1.y = rndf(v1.z); w1.z = rndf(v0.w); w1.w = rndf(v1.w);
        d[j * 2]     = w0;
        d[j * 2 + 1] = w1;
        return;
    }
    __shared__ float tile[32][33];
    const float* src; float* dst; int rows, cols;
    if (z == 0)      { src = Wq; dst = wqT; rows = 4096; cols = 4096; }
    else if (z == 1) { src = Wk; dst = wkT; rows = 4096; cols = 1024; if (blockIdx.x >= 32) return; }
    else if (z == 2) { src = Wv; dst = wvT; rows = 4096; cols = 1024; if (blockIdx.x >= 32) return; }
    else             { src = Wo; dst = woT; rows = 4096; cols = 4096; }
    int c0 = blockIdx.x * 32, r0 = blockIdx.y * 32;
    int x = tid & 31, y0 = tid >> 5;
    int jb = x & 7;
    int px = (x & ~7) + ((jb < 4) ? 2 * jb : 2 * (jb - 4) + 1);
    #pragma unroll
    for (int y = y0; y < 32; y += 8)
        tile[y][x] = src[(size_t)(r0 + y) * cols + c0 + x];
    __syncthreads();
    #pragma unroll
    for (int y = y0; y < 32; y += 8)
        dst[(size_t)(c0 + y) * rows + r0 + px] = rndf(tile[x][y]);
}

// ---------------------------------------------------------------------------
// tf32 mma.sync GEMM core (unchanged from R7).
// ---------------------------------------------------------------------------
#define SA        40
#define STAGE_FLT (2 * 128 * SA)
#define GEMM_SMEM (2 * STAGE_FLT * 4)     // 81920
#define KTILES    (GK / 32)

__device__ __forceinline__ void gemm_core(
    int N, const float* __restrict__ A, const float* __restrict__ BT,
    const float* __restrict__ bias, float* __restrict__ C,
    int m0, int n0, float* sm)
{
    uint32_t sb = smem_to_u32(sm);
    int tid  = threadIdx.x;
    int lane = tid & 31, wid = tid >> 5;
    int wr = wid >> 2, wc = wid & 3;
    int g  = lane >> 2, tg = lane & 3;
    int ldRow = tid >> 3;
    int ldC4  = (tid & 7) * 4;

    float acc[4][4][4];
    #pragma unroll
    for (int i = 0; i < 4; i++)
        #pragma unroll
        for (int j = 0; j < 4; j++)
            #pragma unroll
            for (int k = 0; k < 4; k++) acc[i][j][k] = 0.f;

    auto issue_tile = [&](int kt, int s) {
        const float* Ag = A  + (size_t)(m0) * GK + kt * 32;
        const float* Bg = BT + (size_t)(n0) * GK + kt * 32;
        uint32_t stA = sb + (uint32_t)(s * STAGE_FLT) * 4;
        uint32_t stB = stA + (uint32_t)(128 * SA) * 4;
        #pragma unroll
        for (int i = 0; i < 4; i++) {
            int row = ldRow + 32 * i;
            uint32_t soff = (uint32_t)(row * SA + ldC4) * 4;
            cp_async16(stA + soff, Ag + (size_t)row * GK + ldC4);
            cp_async16(stB + soff, Bg + (size_t)row * GK + ldC4);
        }
    };

    issue_tile(0, 0);
    CP_COMMIT();

    for (int kt = 0; kt < KTILES; kt++) {
        int s = kt & 1;
        CP_WAIT(0);
        __syncthreads();
        if (kt + 1 < KTILES) { issue_tile(kt + 1, s ^ 1); CP_COMMIT(); }

        const float* As = sm + s * STAGE_FLT;
        const float* Bs = As + 128 * SA;

        #pragma unroll
        for (int ks = 0; ks < 4; ks++) {
            int kb = ks * 8 + 2 * tg;
            uint32_t bfr[4][2];
            #pragma unroll
            for (int nt = 0; nt < 4; nt++) {
                float2 lb = *(const float2*)(Bs + (wc * 32 + nt * 8 + g) * SA + kb);
                bfr[nt][0] = __float_as_uint(lb.x);
                bfr[nt][1] = __float_as_uint(lb.y);
            }
            #pragma unroll
            for (int mt = 0; mt < 4; mt++) {
                int ar0 = wr * 64 + mt * 16 + g;
                float2 l0 = *(const float2*)(As + ar0 * SA + kb);
                float2 l1 = *(const float2*)(As + (ar0 + 8) * SA + kb);
                uint32_t a0 = __float_as_uint(l0.x);
                uint32_t a1 = __float_as_uint(l1.x);
                uint32_t a2 = __float_as_uint(l0.y);
                uint32_t a3 = __float_as_uint(l1.y);
                #pragma unroll
                for (int nt = 0; nt < 4; nt++)
                    mma_tf32(acc[mt][nt][0], acc[mt][nt][1], acc[mt][nt][2], acc[mt][nt][3],
                             a0, a1, a2, a3, bfr[nt][0], bfr[nt][1]);
            }
        }
    }

    #pragma unroll
    for (int mt = 0; mt < 4; mt++) {
        int r0 = m0 + wr * 64 + mt * 16 + g;
        #pragma unroll
        for (int nt = 0; nt < 4; nt++) {
            int cc = n0 + wc * 32 + nt * 8 + 2 * tg;
            float2 bv = *(const float2*)(bias + cc);
            float2 o0, o1;
            o0.x = acc[mt][nt][0] + bv.x;
            o0.y = acc[mt][nt][1] + bv.y;
            o1.x = acc[mt][nt][2] + bv.x;
            o1.y = acc[mt][nt][3] + bv.y;
            *(float2*)(C + (size_t)r0 * N + cc)       = o0;
            *(float2*)(C + (size_t)(r0 + 8) * N + cc) = o1;
        }
    }
}

// Launch 2: fused Q+K+V projections
__global__ __launch_bounds__(256, 2) void mma_gemm_qkv(
    const float* __restrict__ Aq, const float* __restrict__ Akv,
    const float* __restrict__ BTq, const float* __restrict__ BTk, const float* __restrict__ BTv,
    const float* __restrict__ bq, const float* __restrict__ bk, const float* __restrict__ bv,
    float* __restrict__ Cq, float* __restrict__ Ck, float* __restrict__ Cv)
{
    extern __shared__ float sm[];
    int bx = blockIdx.x, by = blockIdx.y;
    if (bx < 32)      gemm_core(4096, Aq,  BTq, bq, Cq, by * 128, bx * 128, sm);
    else if (bx < 40) gemm_core(1024, Akv, BTk, bk, Ck, by * 128, (bx - 32) * 128, sm);
    else              gemm_core(1024, Akv, BTv, bv, Cv, by * 128, (bx - 40) * 128, sm);
}

// Launch 6: O projection
__global__ __launch_bounds__(256, 2) void mma_gemm_bias(
    int N, const float* __restrict__ A, const float* __restrict__ BT,
    const float* __restrict__ bias, float* __restrict__ C)
{
    extern __shared__ float sm[];
    gemm_core(N, A, BT, bias, C, blockIdx.y * 128, blockIdx.x * 128, sm);
}

// ---------------------------------------------------------------------------
// Launch 3: RoPE(Q,K) + tf32-round + d-pair-permute (in-place safe: each
// thread owns both 8-blocks it rewrites).
// ---------------------------------------------------------------------------
#define QROWS (B_*T_*H_)      // 131072
#define KROWS (B_*T_*KVH_)    // 32768
#define LOG2_10000_D64 0.20762050593048358f
__global__ void postproc(float* __restrict__ Q, float* __restrict__ K)
{
    long i = (long)blockIdx.x * blockDim.x + threadIdx.x;
    float* X; int hshift; long idx;
    if (i < (long)QROWS * 8) { X = Q; hshift = 5; idx = i; }
    else                     { X = K; hshift = 3; idx = i - (long)QROWS * 8; }
    int j0 = (int)(idx & 7);
    long rh = idx >> 3;
    long row = rh >> hshift;
    int t = (int)(row & (T_ - 1));

    float* p = X + rh * HS_ + j0 * 8;
    float lo[8], hi[8], ol[8], oh[8];
    *(float4*)(lo)     = *(const float4*)(p);
    *(float4*)(lo + 4) = *(const float4*)(p + 4);
    *(float4*)(hi)     = *(const float4*)(p + 64);
    *(float4*)(hi + 4) = *(const float4*)(p + 68);
    #pragma unroll
    for (int jj = 0; jj < 8; jj++) {
        int d = j0 * 8 + jj;
        float inv = exp2f(-(float)d * LOG2_10000_D64);
        float ang = (float)t * inv;
        float c = cosf(ang), s = sinf(ang);
        ol[jj] = rndf(lo[jj] * c - hi[jj] * s);
        oh[jj] = rndf(hi[jj] * c + lo[jj] * s);
    }
    float4 w0, w1;
    w0.x = ol[0]; w0.y = ol[4]; w0.z = ol[1]; w0.w = ol[5];
    w1.x = ol[2]; w1.y = ol[6]; w1.z = ol[3]; w1.w = ol[7];
    *(float4*)(p)     = w0;
    *(float4*)(p + 4) = w1;
    w0.x = oh[0]; w0.y = oh[4]; w0.z = oh[1]; w0.w = oh[5];
    w1.x = oh[2]; w1.y = oh[6]; w1.z = oh[3]; w1.w = oh[7];
    *(float4*)(p + 64) = w0;
    *(float4*)(p + 68) = w1;
}

// ---------------------------------------------------------------------------
// Launch 4: V transpose -> Vt[b][kh][d][t], tf32-rounded, t-pair-permuted.
// ---------------------------------------------------------------------------
__global__ void vtrans_kernel(const float* __restrict__ V, float* __restrict__ Vt)
{
    __shared__ float tile[32][33];
    int z = blockIdx.z;                 // b*KVH + kh
    int b = z >> 3, kh = z & 7;
    int t0 = blockIdx.x * 32, d0 = blockIdx.y * 32;
    int x = threadIdx.x, y0 = threadIdx.y;
    #pragma unroll
    for (int y = y0; y < 32; y += 8)
        tile[y][x] = V[((size_t)(b * T_ + t0 + y) * KVH_ + kh) * HS_ + d0 + x];
    __syncthreads();
    int jb = x & 7;
    int px = (x & ~7) + ((jb < 4) ? 2 * jb : 2 * (jb - 4) + 1);
    #pragma unroll
    for (int y = y0; y < 32; y += 8)
        Vt[((size_t)z * HS_ + d0 + y) * T_ + t0 + px] = rndf(tile[x][y]);
}

// ---------------------------------------------------------------------------
// Launch 5: tensor-core causal flash attention, LDS.64 fragment loads.
// ---------------------------------------------------------------------------
#define KS 136
#define VS 72
#define PS 72
#define OFF_KS0 0
#define OFF_KS1 8704
#define OFF_VS0 17408
#define OFF_VS1 26624
#define OFF_PS  35840
#define ATTN_SMEM (45056 * 4)

__global__ __launch_bounds__(256) void attn_mma(
    const float* __restrict__ Q, const float* __restrict__ K,
    const float* __restrict__ Vt, float* __restrict__ Y)
{
    extern __shared__ float sm[];
    uint32_t sb = smem_to_u32(sm);
    int tid = threadIdx.x, lane = tid & 31, w = tid >> 5;
    int g = lane >> 2, tg = lane & 3;
    int qb = gridDim.x - 1 - blockIdx.x;
    int h = blockIdx.y, b = blockIdx.z;
    int kh = h / GROUPS;
    const float scale = 0.08838834764831845f;
    int r0 = qb * 128 + w * 16 + g;

    // ---- stage Q into smem (K region), extract LDS.64 fragments ----
    for (int i = tid; i < 128 * 32; i += 256) {
        int row = i >> 5, c4 = (i & 31) * 4;
        *(float4*)(sm + row * KS + c4) =
            *(const float4*)(Q + (size_t)(b * T_ + qb * 128 + row) * (H_ * HS_) + h * HS_ + c4);
    }
    __syncthreads();
    uint32_t qf[16][4];
    #pragma unroll
    for (int ks = 0; ks < 16; ks++) {
        int kb = ks * 8 + 2 * tg;
        float2 q0 = *(const float2*)(sm + (w * 16 + g)     * KS + kb);
        float2 q1 = *(const float2*)(sm + (w * 16 + g + 8) * KS + kb);
        qf[ks][0] = f2tf32(q0.x * scale);
        qf[ks][1] = f2tf32(q1.x * scale);
        qf[ks][2] = f2tf32(q0.y * scale);
        qf[ks][3] = f2tf32(q1.y * scale);
    }
    __syncthreads();

    float O[16][4];
    #pragma unroll
    for (int i = 0; i < 16; i++)
        #pragma unroll
        for (int j = 0; j < 4; j++) O[i][j] = 0.f;
    float m0 = -1e30f, m1 = -1e30f, l0 = 0.f, l1 = 0.f;

    int nt = 2 * qb + 2;

    auto issue_kv = [&](int jt, int s) {
        uint32_t kbase = sb + (uint32_t)(s ? OFF_KS1 : OFF_KS0) * 4;
        uint32_t vbase = sb + (uint32_t)(s ? OFF_VS1 : OFF_VS0) * 4;
        const float* Kg  = K + ((size_t)(b * T_ + jt * 64) * KVH_ + kh) * HS_;
        const float* Vg  = Vt + ((size_t)(b * KVH_ + kh) * HS_) * T_ + jt * 64;
        #pragma unroll
        for (int j = 0; j < 8; j++) {
            int ii = tid + 256 * j;
            int krow = ii >> 5, kc4 = (ii & 31) * 4;
            cp_async16(kbase + (uint32_t)(krow * KS + kc4) * 4,
                       Kg + (size_t)krow * (KVH_ * HS_) + kc4);
            int vrow = ii >> 4, vc4 = (ii & 15) * 4;
            cp_async16(vbase + (uint32_t)(vrow * VS + vc4) * 4,
                       Vg + (size_t)vrow * T_ + vc4);
        }
    };

    issue_kv(0, 0);
    CP_COMMIT();

    for (int jt = 0; jt < nt; jt++) {
        if (jt + 1 < nt) issue_kv(jt + 1, (jt + 1) & 1);
        CP_COMMIT();
        CP_WAIT(1);
        __syncthreads();

        const float* Ksm = sm + ((jt & 1) ? OFF_KS1 : OFF_KS0);
        const float* Vsm = sm + ((jt & 1) ? OFF_VS1 : OFF_VS0);

        // ---- S = Q K^T ----
        float S[8][4];
        #pragma unroll
        for (int i = 0; i < 8; i++)
            #pragma unroll
            for (int j = 0; j < 4; j++) S[i][j] = 0.f;

        #pragma unroll
        for (int ks = 0; ks < 16; ks++) {
            int kb = ks * 8 + 2 * tg;
            #pragma unroll
            for (int nf = 0; nf < 8; nf++) {
                float2 lb = *(const float2*)(Ksm + (nf * 8 + g) * KS + kb);
                mma_tf32(S[nf][0], S[nf][1], S[nf][2], S[nf][3],
                         qf[ks][0], qf[ks][1], qf[ks][2], qf[ks][3],
                         __float_as_uint(lb.x), __float_as_uint(lb.y));
            }
        }

        if (jt >= 2 * qb) {
            int cb = jt * 64;
            #pragma unroll
            for (int nf = 0; nf < 8; nf++) {
                int c0 = cb + nf * 8 + 2 * tg, c1 = c0 + 1;
                if (c0 > r0)     S[nf][0] = -1e30f;
                if (c1 > r0)     S[nf][1] = -1e30f;
                if (c0 > r0 + 8) S[nf][2] = -1e30f;
                if (c1 > r0 + 8) S[nf][3] = -1e30f;
            }
        }

        // ---- online softmax ----
        float mx0 = -1e30f, mx1 = -1e30f;
        #pragma unroll
        for (int nf = 0; nf < 8; nf++) {
            mx0 = fmaxf(mx0, fmaxf(S[nf][0], S[nf][1]));
            mx1 = fmaxf(mx1, fmaxf(S[nf][2], S[nf][3]));
        }
        mx0 = fmaxf(mx0, __shfl_xor_sync(0xffffffffu, mx0, 1));
        mx0 = fmaxf(mx0, __shfl_xor_sync(0xffffffffu, mx0, 2));
        mx1 = fmaxf(mx1, __shfl_xor_sync(0xffffffffu, mx1, 1));
        mx1 = fmaxf(mx1, __shfl_xor_sync(0xffffffffu, mx1, 2));

        float mn0 = fmaxf(m0, mx0), mn1 = fmaxf(m1, mx1);
        float a0 = __expf(m0 - mn0), a1 = __expf(m1 - mn1);
        float s0 = 0.f, s1 = 0.f;
        #pragma unroll
        for (int nf = 0; nf < 8; nf++) {
            S[nf][0] = __expf(S[nf][0] - mn0);
            S[nf][1] = __expf(S[nf][1] - mn0);
            S[nf][2] = __expf(S[nf][2] - mn1);
            S[nf][3] = __expf(S[nf][3] - mn1);
            s0 += S[nf][0] + S[nf][1];
            s1 += S[nf][2] + S[nf][3];
        }
        s0 += __shfl_xor_sync(0xffffffffu, s0, 1);
        s0 += __shfl_xor_sync(0xffffffffu, s0, 2);
        s1 += __shfl_xor_sync(0xffffffffu, s1, 1);
        s1 += __shfl_xor_sync(0xffffffffu, s1, 2);
        l0 = l0 * a0 + s0; l1 = l1 * a1 + s1;
        m0 = mn0; m1 = mn1;

        #pragma unroll
        for (int nf2 = 0; nf2 < 16; nf2++) {
            O[nf2][0] *= a0; O[nf2][1] *= a0;
            O[nf2][2] *= a1; O[nf2][3] *= a1;
        }

        // ---- stage P (tf32, t-permuted) ----
        float* Psm = sm + OFF_PS;
        int prow0 = (w * 16 + g) * PS;
        int prow1 = (w * 16 + g + 8) * PS;
        int pc = (tg < 2) ? 4 * tg : 4 * tg - 7;
        #pragma unroll
        for (int nf = 0; nf < 8; nf++) {
            Psm[prow0 + nf * 8 + pc]     = rndf(S[nf][0]);
            Psm[prow0 + nf * 8 + pc + 2] = rndf(S[nf][1]);
            Psm[prow1 + nf * 8 + pc]     = rndf(S[nf][2]);
            Psm[prow1 + nf * 8 + pc + 2] = rndf(S[nf][3]);
        }
        __syncwarp();

        // ---- O += P V (Vt rows = d, LDS.64 everywhere) ----
        #pragma unroll
        for (int ks2 = 0; ks2 < 8; ks2++) {
            int kb2 = ks2 * 8 + 2 * tg;
            float2 pl0 = *(const float2*)(Psm + prow0 + kb2);
            float2 pl1 = *(const float2*)(Psm + prow1 + kb2);
            uint32_t pa0 = __float_as_uint(pl0.x);
            uint32_t pa1 = __float_as_uint(pl1.x);
            uint32_t pa2 = __float_as_uint(pl0.y);
            uint32_t pa3 = __float_as_uint(pl1.y);
            #pragma unroll
            for (int nf2 = 0; nf2 < 16; nf2++) {
                float2 vb = *(const float2*)(Vsm + (nf2 * 8 + g) * VS + kb2);
                mma_tf32(O[nf2][0], O[nf2][1], O[nf2][2], O[nf2][3],
                         pa0, pa1, pa2, pa3,
                         __float_as_uint(vb.x), __float_as_uint(vb.y));
            }
        }
        __syncthreads();
    }

    // ---- epilogue: normalize, tf32-round, store k-permuted ----
    float il0 = 1.f / l0, il1 = 1.f / l1;
    size_t base0 = (size_t)(b * T_ + r0) * (H_ * HS_) + h * HS_;
    size_t base1 = base0 + (size_t)8 * (H_ * HS_);
    int pc = (tg < 2) ? 4 * tg : 4 * tg - 7;
    #pragma unroll
    for (int nf2 = 0; nf2 < 16; nf2++) {
        Y[base0 + nf2 * 8 + pc]     = rndf(O[nf2][0] * il0);
        Y[base0 + nf2 * 8 + pc + 2] = rndf(O[nf2][1] * il0);
        Y[base1 + nf2 * 8 + pc]     = rndf(O[nf2][2] * il1);
        Y[base1 + nf2 * 8 + pc + 2] = rndf(O[nf2][3] * il1);
    }
}

// ---------------------------------------------------------------------------
extern "C" void kernel_launch(void* const* d_in, const int* in_sizes, int n_in,
                              void* d_out, int out_size)
{
    const float* q_x  = (const float*)d_in[0];
    const float* kv_x = (const float*)d_in[1];
    const float* Wq   = (const float*)d_in[2];
    const float* bq   = (const float*)d_in[3];
    const float* Wk   = (const float*)d_in[4];
    const float* bk   = (const float*)d_in[5];
    const float* Wv   = (const float*)d_in[6];
    const float* bv   = (const float*)d_in[7];
    const float* Wo   = (const float*)d_in[8];
    const float* bo   = (const float*)d_in[9];
    float* out = (float*)d_out;

    float *qp, *kp, *vp, *vtp, *yp, *wqT, *wkT, *wvT, *woT, *xq, *xkv;
    cudaGetSymbolAddress((void**)&qp, g_Q);
    cudaGetSymbolAddress((void**)&kp, g_K);
    cudaGetSymbolAddress((void**)&vp, g_V);
    cudaGetSymbolAddress((void**)&vtp, g_Vt);
    cudaGetSymbolAddress((void**)&yp, g_Y);
    cudaGetSymbolAddress((void**)&wqT, g_WqT);
    cudaGetSymbolAddress((void**)&wkT, g_WkT);
    cudaGetSymbolAddress((void**)&wvT, g_WvT);
    cudaGetSymbolAddress((void**)&woT, g_WoT);
    cudaGetSymbolAddress((void**)&xq, g_Xq);
    cudaGetSymbolAddress((void**)&xkv, g_Xkv);

    const int M = B_ * T_;

    cudaFuncSetAttribute(mma_gemm_qkv, cudaFuncAttributeMaxDynamicSharedMemorySize, GEMM_SMEM);
    cudaFuncSetAttribute(mma_gemm_bias, cudaFuncAttributeMaxDynamicSharedMemorySize, GEMM_SMEM);
    cudaFuncSetAttribute(attn_mma, cudaFuncAttributeMaxDynamicSharedMemorySize, ATTN_SMEM);

    prep_kernel<<<dim3(128, 128, 5), 256>>>(Wq, Wk, Wv, Wo, wqT, wkT, wvT, woT,
                                            (const float4*)q_x, (const float4*)kv_x,
                                            (float4*)xq, (float4*)xkv);
    mma_gemm_qkv<<<dim3(48, M / 128), 256, GEMM_SMEM>>>(xq, xkv, wqT, wkT, wvT,
                                                        bq, bk, bv, qp, kp, vp);
    postproc<<<(unsigned)(((long)(QROWS + KROWS) * 8) / 256), 256>>>(qp, kp);
    vtrans_kernel<<<dim3(T_ / 32, HS_ / 32, B_ * KVH_), dim3(32, 8)>>>(vp, vtp);
    attn_mma<<<dim3(T_ / 128, H_, B_), 256, ATTN_SMEM>>>(qp, kp, vtp, yp);
    mma_gemm_bias<<<dim3(C_ / 128, M / 128), 256, GEMM_SMEM>>>(C_, yp, woT, bo, out);
}

// round 9
// speedup vs baseline: 5.1382x; 1.0145x over previous
#include <cuda_runtime.h>
#include <math.h>
#include <cstdint>

#define B_   2
#define T_   2048
#define C_   4096
#define H_   32
#define KVH_ 8
#define HS_  128
#define GROUPS (H_/KVH_)
#define GK    4096

// ---------------------------------------------------------------------------
// Scratch
// ---------------------------------------------------------------------------
__device__ float g_Q[(size_t)B_*T_*H_*HS_];      // d-permuted after postproc
__device__ float g_K[(size_t)B_*T_*KVH_*HS_];    // d-permuted after postproc
__device__ float g_V[(size_t)B_*T_*KVH_*HS_];    // raw from gemm
__device__ float g_Vt[(size_t)B_*KVH_*HS_*T_];   // V^T, t-permuted, tf32
__device__ float g_Y[(size_t)B_*T_*H_*HS_];      // k-permuted layout
__device__ float g_WqT[(size_t)C_*H_*HS_];       // [N][K], K k-permuted
__device__ float g_WkT[(size_t)C_*KVH_*HS_];
__device__ float g_WvT[(size_t)C_*KVH_*HS_];
__device__ float g_WoT[(size_t)H_*HS_*C_];
__device__ float g_Xq[(size_t)B_*T_*C_];         // tf32-rounded + k-permuted
__device__ float g_Xkv[(size_t)B_*T_*C_];

// ---------------------------------------------------------------------------
// Helpers
// ---------------------------------------------------------------------------
__device__ __forceinline__ uint32_t smem_to_u32(const void* p) {
    uint32_t a;
    asm("{ .reg .u64 t; cvta.to.shared.u64 t, %1; cvt.u32.u64 %0, t; }" : "=r"(a) : "l"(p));
    return a;
}
__device__ __forceinline__ uint32_t f2tf32(float x) {
    uint32_t u;
    asm("cvt.rna.tf32.f32 %0, %1;" : "=r"(u) : "f"(x));
    return u;
}
__device__ __forceinline__ float rndf(float x) { return __uint_as_float(f2tf32(x)); }

__device__ __forceinline__ void cp_async16(uint32_t smem_addr, const void* gptr) {
    asm volatile("cp.async.cg.shared.global [%0], [%1], 16;" :: "r"(smem_addr), "l"(gptr));
}
#define CP_COMMIT() asm volatile("cp.async.commit_group;" ::: "memory")
#define CP_WAIT(n)  asm volatile("cp.async.wait_group %0;" :: "n"(n) : "memory")

__device__ __forceinline__ void mma_tf32(
    float& d0, float& d1, float& d2, float& d3,
    uint32_t a0, uint32_t a1, uint32_t a2, uint32_t a3,
    uint32_t b0, uint32_t b1)
{
    asm volatile(
        "mma.sync.aligned.m16n8k8.row.col.f32.tf32.tf32.f32 "
        "{%0,%1,%2,%3}, {%4,%5,%6,%7}, {%8,%9}, {%0,%1,%2,%3};"
        : "+f"(d0), "+f"(d1), "+f"(d2), "+f"(d3)
        : "r"(a0), "r"(a1), "r"(a2), "r"(a3), "r"(b0), "r"(b1));
}

// ---------------------------------------------------------------------------
// Launch 1: merged prep (weight transposes + input round/permute)
// ---------------------------------------------------------------------------
#define N8IN 2097152L   // 4096*4096/8
__global__ void prep_kernel(
    const float* __restrict__ Wq, const float* __restrict__ Wk,
    const float* __restrict__ Wv, const float* __restrict__ Wo,
    float* __restrict__ wqT, float* __restrict__ wkT,
    float* __restrict__ wvT, float* __restrict__ woT,
    const float4* __restrict__ qx, const float4* __restrict__ kvx,
    float4* __restrict__ oq, float4* __restrict__ okv)
{
    int z = blockIdx.z;
    int tid = threadIdx.x;
    if (z == 4) {
        long i = ((long)(blockIdx.y * 128 + blockIdx.x)) * 256 + tid;
        const float4* s; float4* d; long j;
        if (i < N8IN) { s = qx; d = oq; j = i; }
        else          { s = kvx; d = okv; j = i - N8IN; }
        float4 v0 = s[j * 2], v1 = s[j * 2 + 1];
        float4 w0, w1;
        w0.x = rndf(v0.x); w0.y = rndf(v1.x); w0.z = rndf(v0.y); w0.w = rndf(v1.y);
        w1.x = rndf(v0.z); w1.y = rndf(v1.z); w1.z = rndf(v0.w); w1.w = rndf(v1.w);
        d[j * 2]     = w0;
        d[j * 2 + 1] = w1;
        return;
    }
    __shared__ float tile[32][33];
    const float* src; float* dst; int rows, cols;
    if (z == 0)      { src = Wq; dst = wqT; rows = 4096; cols = 4096; }
    else if (z == 1) { src = Wk; dst = wkT; rows = 4096; cols = 1024; if (blockIdx.x >= 32) return; }
    else if (z == 2) { src = Wv; dst = wvT; rows = 4096; cols = 1024; if (blockIdx.x >= 32) return; }
    else             { src = Wo; dst = woT; rows = 4096; cols = 4096; }
    int c0 = blockIdx.x * 32, r0 = blockIdx.y * 32;
    int x = tid & 31, y0 = tid >> 5;
    int jb = x & 7;
    int px = (x & ~7) + ((jb < 4) ? 2 * jb : 2 * (jb - 4) + 1);
    #pragma unroll
    for (int y = y0; y < 32; y += 8)
        tile[y][x] = src[(size_t)(r0 + y) * cols + c0 + x];
    __syncthreads();
    #pragma unroll
    for (int y = y0; y < 32; y += 8)
        dst[(size_t)(c0 + y) * rows + r0 + px] = rndf(tile[x][y]);
}

// ---------------------------------------------------------------------------
// tf32 mma.sync GEMM core (unchanged).
// ---------------------------------------------------------------------------
#define SA        40
#define STAGE_FLT (2 * 128 * SA)
#define GEMM_SMEM (2 * STAGE_FLT * 4)     // 81920
#define KTILES    (GK / 32)

__device__ __forceinline__ void gemm_core(
    int N, const float* __restrict__ A, const float* __restrict__ BT,
    const float* __restrict__ bias, float* __restrict__ C,
    int m0, int n0, float* sm)
{
    uint32_t sb = smem_to_u32(sm);
    int tid  = threadIdx.x;
    int lane = tid & 31, wid = tid >> 5;
    int wr = wid >> 2, wc = wid & 3;
    int g  = lane >> 2, tg = lane & 3;
    int ldRow = tid >> 3;
    int ldC4  = (tid & 7) * 4;

    float acc[4][4][4];
    #pragma unroll
    for (int i = 0; i < 4; i++)
        #pragma unroll
        for (int j = 0; j < 4; j++)
            #pragma unroll
            for (int k = 0; k < 4; k++) acc[i][j][k] = 0.f;

    auto issue_tile = [&](int kt, int s) {
        const float* Ag = A  + (size_t)(m0) * GK + kt * 32;
        const float* Bg = BT + (size_t)(n0) * GK + kt * 32;
        uint32_t stA = sb + (uint32_t)(s * STAGE_FLT) * 4;
        uint32_t stB = stA + (uint32_t)(128 * SA) * 4;
        #pragma unroll
        for (int i = 0; i < 4; i++) {
            int row = ldRow + 32 * i;
            uint32_t soff = (uint32_t)(row * SA + ldC4) * 4;
            cp_async16(stA + soff, Ag + (size_t)row * GK + ldC4);
            cp_async16(stB + soff, Bg + (size_t)row * GK + ldC4);
        }
    };

    issue_tile(0, 0);
    CP_COMMIT();

    for (int kt = 0; kt < KTILES; kt++) {
        int s = kt & 1;
        CP_WAIT(0);
        __syncthreads();
        if (kt + 1 < KTILES) { issue_tile(kt + 1, s ^ 1); CP_COMMIT(); }

        const float* As = sm + s * STAGE_FLT;
        const float* Bs = As + 128 * SA;

        #pragma unroll
        for (int ks = 0; ks < 4; ks++) {
            int kb = ks * 8 + 2 * tg;
            uint32_t bfr[4][2];
            #pragma unroll
            for (int nt = 0; nt < 4; nt++) {
                float2 lb = *(const float2*)(Bs + (wc * 32 + nt * 8 + g) * SA + kb);
                bfr[nt][0] = __float_as_uint(lb.x);
                bfr[nt][1] = __float_as_uint(lb.y);
            }
            #pragma unroll
            for (int mt = 0; mt < 4; mt++) {
                int ar0 = wr * 64 + mt * 16 + g;
                float2 l0 = *(const float2*)(As + ar0 * SA + kb);
                float2 l1 = *(const float2*)(As + (ar0 + 8) * SA + kb);
                uint32_t a0 = __float_as_uint(l0.x);
                uint32_t a1 = __float_as_uint(l1.x);
                uint32_t a2 = __float_as_uint(l0.y);
                uint32_t a3 = __float_as_uint(l1.y);
                #pragma unroll
                for (int nt = 0; nt < 4; nt++)
                    mma_tf32(acc[mt][nt][0], acc[mt][nt][1], acc[mt][nt][2], acc[mt][nt][3],
                             a0, a1, a2, a3, bfr[nt][0], bfr[nt][1]);
            }
        }
    }

    #pragma unroll
    for (int mt = 0; mt < 4; mt++) {
        int r0 = m0 + wr * 64 + mt * 16 + g;
        #pragma unroll
        for (int nt = 0; nt < 4; nt++) {
            int cc = n0 + wc * 32 + nt * 8 + 2 * tg;
            float2 bv = *(const float2*)(bias + cc);
            float2 o0, o1;
            o0.x = acc[mt][nt][0] + bv.x;
            o0.y = acc[mt][nt][1] + bv.y;
            o1.x = acc[mt][nt][2] + bv.x;
            o1.y = acc[mt][nt][3] + bv.y;
            *(float2*)(C + (size_t)r0 * N + cc)       = o0;
            *(float2*)(C + (size_t)(r0 + 8) * N + cc) = o1;
        }
    }
}

// Launch 2: fused Q+K+V projections
__global__ __launch_bounds__(256, 2) void mma_gemm_qkv(
    const float* __restrict__ Aq, const float* __restrict__ Akv,
    const float* __restrict__ BTq, const float* __restrict__ BTk, const float* __restrict__ BTv,
    const float* __restrict__ bq, const float* __restrict__ bk, const float* __restrict__ bv,
    float* __restrict__ Cq, float* __restrict__ Ck, float* __restrict__ Cv)
{
    extern __shared__ float sm[];
    int bx = blockIdx.x, by = blockIdx.y;
    if (bx < 32)      gemm_core(4096, Aq,  BTq, bq, Cq, by * 128, bx * 128, sm);
    else if (bx < 40) gemm_core(1024, Akv, BTk, bk, Ck, by * 128, (bx - 32) * 128, sm);
    else              gemm_core(1024, Akv, BTv, bv, Cv, by * 128, (bx - 40) * 128, sm);
}

// Launch 6: O projection
__global__ __launch_bounds__(256, 2) void mma_gemm_bias(
    int N, const float* __restrict__ A, const float* __restrict__ BT,
    const float* __restrict__ bias, float* __restrict__ C)
{
    extern __shared__ float sm[];
    gemm_core(N, A, BT, bias, C, blockIdx.y * 128, blockIdx.x * 128, sm);
}

// ---------------------------------------------------------------------------
// Launch 3: RoPE(Q,K) + tf32-round + d-pair-permute (in-place safe).
// ---------------------------------------------------------------------------
#define QROWS (B_*T_*H_)      // 131072
#define KROWS (B_*T_*KVH_)    // 32768
#define LOG2_10000_D64 0.20762050593048358f
__global__ void postproc(float* __restrict__ Q, float* __restrict__ K)
{
    long i = (long)blockIdx.x * blockDim.x + threadIdx.x;
    float* X; int hshift; long idx;
    if (i < (long)QROWS * 8) { X = Q; hshift = 5; idx = i; }
    else                     { X = K; hshift = 3; idx = i - (long)QROWS * 8; }
    int j0 = (int)(idx & 7);
    long rh = idx >> 3;
    long row = rh >> hshift;
    int t = (int)(row & (T_ - 1));

    float* p = X + rh * HS_ + j0 * 8;
    float lo[8], hi[8], ol[8], oh[8];
    *(float4*)(lo)     = *(const float4*)(p);
    *(float4*)(lo + 4) = *(const float4*)(p + 4);
    *(float4*)(hi)     = *(const float4*)(p + 64);
    *(float4*)(hi + 4) = *(const float4*)(p + 68);
    #pragma unroll
    for (int jj = 0; jj < 8; jj++) {
        int d = j0 * 8 + jj;
        float inv = exp2f(-(float)d * LOG2_10000_D64);
        float ang = (float)t * inv;
        float c = cosf(ang), s = sinf(ang);
        ol[jj] = rndf(lo[jj] * c - hi[jj] * s);
        oh[jj] = rndf(hi[jj] * c + lo[jj] * s);
    }
    float4 w0, w1;
    w0.x = ol[0]; w0.y = ol[4]; w0.z = ol[1]; w0.w = ol[5];
    w1.x = ol[2]; w1.y = ol[6]; w1.z = ol[3]; w1.w = ol[7];
    *(float4*)(p)     = w0;
    *(float4*)(p + 4) = w1;
    w0.x = oh[0]; w0.y = oh[4]; w0.z = oh[1]; w0.w = oh[5];
    w1.x = oh[2]; w1.y = oh[6]; w1.z = oh[3]; w1.w = oh[7];
    *(float4*)(p + 64) = w0;
    *(float4*)(p + 68) = w1;
}

// ---------------------------------------------------------------------------
// Launch 4: V transpose -> Vt[b][kh][d][t], tf32-rounded, t-pair-permuted.
// ---------------------------------------------------------------------------
__global__ void vtrans_kernel(const float* __restrict__ V, float* __restrict__ Vt)
{
    __shared__ float tile[32][33];
    int z = blockIdx.z;
    int b = z >> 3, kh = z & 7;
    int t0 = blockIdx.x * 32, d0 = blockIdx.y * 32;
    int x = threadIdx.x, y0 = threadIdx.y;
    #pragma unroll
    for (int y = y0; y < 32; y += 8)
        tile[y][x] = V[((size_t)(b * T_ + t0 + y) * KVH_ + kh) * HS_ + d0 + x];
    __syncthreads();
    int jb = x & 7;
    int px = (x & ~7) + ((jb < 4) ? 2 * jb : 2 * (jb - 4) + 1);
    #pragma unroll
    for (int y = y0; y < 32; y += 8)
        Vt[((size_t)z * HS_ + d0 + y) * T_ + t0 + px] = rndf(tile[x][y]);
}

// ---------------------------------------------------------------------------
// Launch 5: tensor-core causal flash attention.
// P via register shuffles (no smem staging); single sync per tile.
// ---------------------------------------------------------------------------
#define KS 136
#define VS 72
#define OFF_KS0 0
#define OFF_KS1 8704
#define OFF_VS0 17408
#define OFF_VS1 26624
#define ATTN_SMEM (35840 * 4)

__global__ __launch_bounds__(256) void attn_mma(
    const float* __restrict__ Q, const float* __restrict__ K,
    const float* __restrict__ Vt, float* __restrict__ Y)
{
    extern __shared__ float sm[];
    uint32_t sb = smem_to_u32(sm);
    int tid = threadIdx.x, lane = tid & 31, w = tid >> 5;
    int g = lane >> 2, tg = lane & 3;
    int qb = gridDim.x - 1 - blockIdx.x;
    int h = blockIdx.y, b = blockIdx.z;
    int kh = h / GROUPS;
    const float scale = 0.08838834764831845f;
    int r0 = qb * 128 + w * 16 + g;

    // ---- stage Q into smem (K region), extract LDS.64 fragments ----
    for (int i = tid; i < 128 * 32; i += 256) {
        int row = i >> 5, c4 = (i & 31) * 4;
        *(float4*)(sm + row * KS + c4) =
            *(const float4*)(Q + (size_t)(b * T_ + qb * 128 + row) * (H_ * HS_) + h * HS_ + c4);
    }
    __syncthreads();
    uint32_t qf[16][4];
    #pragma unroll
    for (int ks = 0; ks < 16; ks++) {
        int kb = ks * 8 + 2 * tg;
        float2 q0 = *(const float2*)(sm + (w * 16 + g)     * KS + kb);
        float2 q1 = *(const float2*)(sm + (w * 16 + g + 8) * KS + kb);
        qf[ks][0] = f2tf32(q0.x * scale);
        qf[ks][1] = f2tf32(q1.x * scale);
        qf[ks][2] = f2tf32(q0.y * scale);
        qf[ks][3] = f2tf32(q1.y * scale);
    }
    __syncthreads();

    float O[16][4];
    #pragma unroll
    for (int i = 0; i < 16; i++)
        #pragma unroll
        for (int j = 0; j < 4; j++) O[i][j] = 0.f;
    float m0 = -1e30f, m1 = -1e30f, l0 = 0.f, l1 = 0.f;

    int nt = 2 * qb + 2;

    auto issue_kv = [&](int jt, int s) {
        uint32_t kbase = sb + (uint32_t)(s ? OFF_KS1 : OFF_KS0) * 4;
        uint32_t vbase = sb + (uint32_t)(s ? OFF_VS1 : OFF_VS0) * 4;
        const float* Kg  = K + ((size_t)(b * T_ + jt * 64) * KVH_ + kh) * HS_;
        const float* Vg  = Vt + ((size_t)(b * KVH_ + kh) * HS_) * T_ + jt * 64;
        #pragma unroll
        for (int j = 0; j < 8; j++) {
            int ii = tid + 256 * j;
            int krow = ii >> 5, kc4 = (ii & 31) * 4;
            cp_async16(kbase + (uint32_t)(krow * KS + kc4) * 4,
                       Kg + (size_t)krow * (KVH_ * HS_) + kc4);
            int vrow = ii >> 4, vc4 = (ii & 15) * 4;
            cp_async16(vbase + (uint32_t)(vrow * VS + vc4) * 4,
                       Vg + (size_t)vrow * T_ + vc4);
        }
    };

    issue_kv(0, 0);
    CP_COMMIT();

    for (int jt = 0; jt < nt; jt++) {
        int s = jt & 1;
        CP_WAIT(0);           // tile jt complete (only group in flight)
        __syncthreads();      // publishes jt; proves jt-1 reads done -> other buf free
        if (jt + 1 < nt) { issue_kv(jt + 1, s ^ 1); CP_COMMIT(); }

        const float* Ksm = sm + (s ? OFF_KS1 : OFF_KS0);
        const float* Vsm = sm + (s ? OFF_VS1 : OFF_VS0);

        // ---- S = Q K^T ----
        float S[8][4];
        #pragma unroll
        for (int i = 0; i < 8; i++)
            #pragma unroll
            for (int j = 0; j < 4; j++) S[i][j] = 0.f;

        #pragma unroll
        for (int ks = 0; ks < 16; ks++) {
            int kb = ks * 8 + 2 * tg;
            #pragma unroll
            for (int nf = 0; nf < 8; nf++) {
                float2 lb = *(const float2*)(Ksm + (nf * 8 + g) * KS + kb);
                mma_tf32(S[nf][0], S[nf][1], S[nf][2], S[nf][3],
                         qf[ks][0], qf[ks][1], qf[ks][2], qf[ks][3],
                         __float_as_uint(lb.x), __float_as_uint(lb.y));
            }
        }

        if (jt >= 2 * qb) {
            int cb = jt * 64;
            #pragma unroll
            for (int nf = 0; nf < 8; nf++) {
                int c0 = cb + nf * 8 + 2 * tg, c1 = c0 + 1;
                if (c0 > r0)     S[nf][0] = -1e30f;
                if (c1 > r0)     S[nf][1] = -1e30f;
                if (c0 > r0 + 8) S[nf][2] = -1e30f;
                if (c1 > r0 + 8) S[nf][3] = -1e30f;
            }
        }

        // ---- online softmax ----
        float mx0 = -1e30f, mx1 = -1e30f;
        #pragma unroll
        for (int nf = 0; nf < 8; nf++) {
            mx0 = fmaxf(mx0, fmaxf(S[nf][0], S[nf][1]));
            mx1 = fmaxf(mx1, fmaxf(S[nf][2], S[nf][3]));
        }
        mx0 = fmaxf(mx0, __shfl_xor_sync(0xffffffffu, mx0, 1));
        mx0 = fmaxf(mx0, __shfl_xor_sync(0xffffffffu, mx0, 2));
        mx1 = fmaxf(mx1, __shfl_xor_sync(0xffffffffu, mx1, 1));
        mx1 = fmaxf(mx1, __shfl_xor_sync(0xffffffffu, mx1, 2));

        float mn0 = fmaxf(m0, mx0), mn1 = fmaxf(m1, mx1);
        float a0 = __expf(m0 - mn0), a1 = __expf(m1 - mn1);
        float s0 = 0.f, s1 = 0.f;
        #pragma unroll
        for (int nf = 0; nf < 8; nf++) {
            S[nf][0] = __expf(S[nf][0] - mn0);
            S[nf][1] = __expf(S[nf][1] - mn0);
            S[nf][2] = __expf(S[nf][2] - mn1);
            S[nf][3] = __expf(S[nf][3] - mn1);
            s0 += S[nf][0] + S[nf][1];
            s1 += S[nf][2] + S[nf][3];
        }
        s0 += __shfl_xor_sync(0xffffffffu, s0, 1);
        s0 += __shfl_xor_sync(0xffffffffu, s0, 2);
        s1 += __shfl_xor_sync(0xffffffffu, s1, 1);
        s1 += __shfl_xor_sync(0xffffffffu, s1, 2);
        l0 = l0 * a0 + s0; l1 = l1 * a1 + s1;
        m0 = mn0; m1 = mn1;

        #pragma unroll
        for (int nf2 = 0; nf2 < 16; nf2++) {
            O[nf2][0] *= a0; O[nf2][1] *= a0;
            O[nf2][2] *= a1; O[nf2][3] *= a1;
        }

        // ---- O += P V : P A-frags assembled via quad shuffles ----
        int src0 = (lane & 28) | (tg >> 1);
        int src1 = src0 + 2;
        #pragma unroll
        for (int kb2 = 0; kb2 < 8; kb2++) {
            float p00 = __shfl_sync(0xffffffffu, S[kb2][0], src0);
            float p01 = __shfl_sync(0xffffffffu, S[kb2][1], src0);
            float p10 = __shfl_sync(0xffffffffu, S[kb2][2], src0);
            float p11 = __shfl_sync(0xffffffffu, S[kb2][3], src0);
            float r00 = __shfl_sync(0xffffffffu, S[kb2][0], src1);
            float r01 = __shfl_sync(0xffffffffu, S[kb2][1], src1);
            float r10 = __shfl_sync(0xffffffffu, S[kb2][2], src1);
            float r11 = __shfl_sync(0xffffffffu, S[kb2][3], src1);
            int odd = tg & 1;
            uint32_t pa0 = f2tf32(odd ? p01 : p00);   // row g,   t = tg
            uint32_t pa1 = f2tf32(odd ? p11 : p10);   // row g+8, t = tg
            uint32_t pa2 = f2tf32(odd ? r01 : r00);   // row g,   t = tg+4
            uint32_t pa3 = f2tf32(odd ? r11 : r10);   // row g+8, t = tg+4
            int vb_off = kb2 * 8 + 2 * tg;
            #pragma unroll
            for (int nf2 = 0; nf2 < 16; nf2++) {
                float2 vb = *(const float2*)(Vsm + (nf2 * 8 + g) * VS + vb_off);
                mma_tf32(O[nf2][0], O[nf2][1], O[nf2][2], O[nf2][3],
                         pa0, pa1, pa2, pa3,
                         __float_as_uint(vb.x), __float_as_uint(vb.y));
            }
        }
    }

    // ---- epilogue: normalize, tf32-round, store k-permuted ----
    float il0 = 1.f / l0, il1 = 1.f / l1;
    size_t base0 = (size_t)(b * T_ + r0) * (H_ * HS_) + h * HS_;
    size_t base1 = base0 + (size_t)8 * (H_ * HS_);
    int pc = (tg < 2) ? 4 * tg : 4 * tg - 7;
    #pragma unroll
    for (int nf2 = 0; nf2 < 16; nf2++) {
        Y[base0 + nf2 * 8 + pc]     = rndf(O[nf2][0] * il0);
        Y[base0 + nf2 * 8 + pc + 2] = rndf(O[nf2][1] * il0);
        Y[base1 + nf2 * 8 + pc]     = rndf(O[nf2][2] * il1);
        Y[base1 + nf2 * 8 + pc + 2] = rndf(O[nf2][3] * il1);
    }
}

// ---------------------------------------------------------------------------
extern "C" void kernel_launch(void* const* d_in, const int* in_sizes, int n_in,
                              void* d_out, int out_size)
{
    const float* q_x  = (const float*)d_in[0];
    const float* kv_x = (const float*)d_in[1];
    const float* Wq   = (const float*)d_in[2];
    const float* bq   = (const float*)d_in[3];
    const float* Wk   = (const float*)d_in[4];
    const float* bk   = (const float*)d_in[5];
    const float* Wv   = (const float*)d_in[6];
    const float* bv   = (const float*)d_in[7];
    const float* Wo   = (const float*)d_in[8];
    const float* bo   = (const float*)d_in[9];
    float* out = (float*)d_out;

    float *qp, *kp, *vp, *vtp, *yp, *wqT, *wkT, *wvT, *woT, *xq, *xkv;
    cudaGetSymbolAddress((void**)&qp, g_Q);
    cudaGetSymbolAddress((void**)&kp, g_K);
    cudaGetSymbolAddress((void**)&vp, g_V);
    cudaGetSymbolAddress((void**)&vtp, g_Vt);
    cudaGetSymbolAddress((void**)&yp, g_Y);
    cudaGetSymbolAddress((void**)&wqT, g_WqT);
    cudaGetSymbolAddress((void**)&wkT, g_WkT);
    cudaGetSymbolAddress((void**)&wvT, g_WvT);
    cudaGetSymbolAddress((void**)&woT, g_WoT);
    cudaGetSymbolAddress((void**)&xq, g_Xq);
    cudaGetSymbolAddress((void**)&xkv, g_Xkv);

    const int M = B_ * T_;

    cudaFuncSetAttribute(mma_gemm_qkv, cudaFuncAttributeMaxDynamicSharedMemorySize, GEMM_SMEM);
    cudaFuncSetAttribute(mma_gemm_bias, cudaFuncAttributeMaxDynamicSharedMemorySize, GEMM_SMEM);
    cudaFuncSetAttribute(attn_mma, cudaFuncAttributeMaxDynamicSharedMemorySize, ATTN_SMEM);

    prep_kernel<<<dim3(128, 128, 5), 256>>>(Wq, Wk, Wv, Wo, wqT, wkT, wvT, woT,
                                            (const float4*)q_x, (const float4*)kv_x,
                                            (float4*)xq, (float4*)xkv);
    mma_gemm_qkv<<<dim3(48, M / 128), 256, GEMM_SMEM>>>(xq, xkv, wqT, wkT, wvT,
                                                        bq, bk, bv, qp, kp, vp);
    postproc<<<(unsigned)(((long)(QROWS + KROWS) * 8) / 256), 256>>>(qp, kp);
    vtrans_kernel<<<dim3(T_ / 32, HS_ / 32, B_ * KVH_), dim3(32, 8)>>>(vp, vtp);
    attn_mma<<<dim3(T_ / 128, H_, B_), 256, ATTN_SMEM>>>(qp, kp, vtp, yp);
    mma_gemm_bias<<<dim3(C_ / 128, M / 128), 256, GEMM_SMEM>>>(C_, yp, woT, bo, out);
}